// round 14
// baseline (speedup 1.0000x reference)
#include <cuda_runtime.h>
#include <cuda_bf16.h>
#include <cstdint>
#include <math.h>

#define SEQ     2048
#define BATCH   2
#define DMODEL  768
#define NH      12
#define HD      64
#define NTOK    (SEQ*BATCH)   // 4096
#define NQKV    (3*DMODEL)    // 2304
#define NQB64   (SEQ/64)      // 32 q-blocks of 64 rows

// ---------------------------------------------------------------------------
// Scratch (__device__ globals; allocation-free rule)
// ---------------------------------------------------------------------------
__device__ __nv_bfloat16 g_xs_hi[NTOK*DMODEL];
__device__ __nv_bfloat16 g_xs_lo[NTOK*DMODEL];
__device__ __nv_bfloat16 g_qkvh[NTOK*NQKV];
__device__ __nv_bfloat16 g_qkvl[NTOK*NQKV];
__device__ __nv_bfloat16 g_ys_hi[NTOK*DMODEL];
__device__ __nv_bfloat16 g_ys_lo[NTOK*DMODEL];
__device__ __nv_bfloat16 g_wt_hi[4*DMODEL*DMODEL];   // transposed [N][K]; q,k,v,o slabs
__device__ __nv_bfloat16 g_wt_lo[4*DMODEL*DMODEL];
__device__ float g_bqkv[NQKV];

// ---------------------------------------------------------------------------
// Helpers (baseline PTX only — nothing sm_103a-gated)
// ---------------------------------------------------------------------------
__device__ __forceinline__ uint32_t smem_u32(const void* p) {
    uint32_t a;
    asm("{ .reg .u64 t; cvta.to.shared.u64 t, %1; cvt.u32.u64 %0, t; }" : "=r"(a) : "l"(p));
    return a;
}
#define SWZ128(o) ((o) ^ (((o) >> 3) & 0x70))

__device__ __forceinline__ void ldsm_x4(uint32_t* r, uint32_t addr) {
    asm volatile("ldmatrix.sync.aligned.m8n8.x4.shared.b16 {%0,%1,%2,%3}, [%4];"
        : "=r"(r[0]), "=r"(r[1]), "=r"(r[2]), "=r"(r[3]) : "r"(addr));
}
__device__ __forceinline__ void ldsm_x4_t(uint32_t* r, uint32_t addr) {
    asm volatile("ldmatrix.sync.aligned.m8n8.x4.trans.shared.b16 {%0,%1,%2,%3}, [%4];"
        : "=r"(r[0]), "=r"(r[1]), "=r"(r[2]), "=r"(r[3]) : "r"(addr));
}
__device__ __forceinline__ void mma_bf16(float* c, const uint32_t* a, const uint32_t* b) {
    asm volatile("mma.sync.aligned.m16n8k16.row.col.f32.bf16.bf16.f32 "
        "{%0,%1,%2,%3}, {%4,%5,%6,%7}, {%8,%9}, {%0,%1,%2,%3};"
        : "+f"(c[0]), "+f"(c[1]), "+f"(c[2]), "+f"(c[3])
        : "r"(a[0]), "r"(a[1]), "r"(a[2]), "r"(a[3]), "r"(b[0]), "r"(b[1]));
}
__device__ __forceinline__ void split2(float a, float b, uint32_t& hi, uint32_t& lo) {
    __nv_bfloat162 h = __floats2bfloat162_rn(a, b);
    __nv_bfloat162 l = __floats2bfloat162_rn(a - __bfloat162float(h.x),
                                             b - __bfloat162float(h.y));
    hi = *reinterpret_cast<uint32_t*>(&h);
    lo = *reinterpret_cast<uint32_t*>(&l);
}
__device__ __forceinline__ void cp16(uint32_t saddr, const void* g) {
    asm volatile("cp.async.cg.shared.global [%0], [%1], 16;" :: "r"(saddr), "l"(g) : "memory");
}
__device__ __forceinline__ void cp_commit() {
    asm volatile("cp.async.commit_group;" ::: "memory");
}
template<int N> __device__ __forceinline__ void cp_wait() {
    asm volatile("cp.async.wait_group %0;" :: "n"(N) : "memory");
}

// ---------------------------------------------------------------------------
// Conversion kernels
// ---------------------------------------------------------------------------
__global__ __launch_bounds__(256) void fsplit_kernel(
    const float* __restrict__ in, __nv_bfloat16* __restrict__ hi,
    __nv_bfloat16* __restrict__ lo, int n4)
{
    int i = (blockIdx.x * 256 + threadIdx.x) * 4;
    if (i >= n4 * 4) return;
    float4 f = *(const float4*)&in[i];
    uint32_t h0, l0, h1, l1;
    split2(f.x, f.y, h0, l0);
    split2(f.z, f.w, h1, l1);
    reinterpret_cast<uint32_t*>(hi + i)[0] = h0;
    reinterpret_cast<uint32_t*>(hi + i)[1] = h1;
    reinterpret_cast<uint32_t*>(lo + i)[0] = l0;
    reinterpret_cast<uint32_t*>(lo + i)[1] = l1;
}

// All 4 weights in one launch: z picks W; W[K][N] -> out[n*768 + k] (B^T) hi/lo.
// z==0 (Wq): values pre-scaled by 0.125 (folds 1/sqrt(d_k) into q; exact pow2).
__global__ __launch_bounds__(256) void wtsplit_kernel(
    const float* __restrict__ W0, const float* __restrict__ W1,
    const float* __restrict__ W2, const float* __restrict__ W3,
    __nv_bfloat16* __restrict__ th_base, __nv_bfloat16* __restrict__ tl_base)
{
    const float* W = (blockIdx.z == 0) ? W0 : (blockIdx.z == 1) ? W1
                   : (blockIdx.z == 2) ? W2 : W3;
    const float sc = (blockIdx.z == 0) ? 0.125f : 1.0f;
    __nv_bfloat16* th = th_base + (size_t)blockIdx.z * DMODEL * DMODEL;
    __nv_bfloat16* tl = tl_base + (size_t)blockIdx.z * DMODEL * DMODEL;

    __shared__ float t[32][33];
    int n0 = blockIdx.x * 32, k0 = blockIdx.y * 32;
    int tx = threadIdx.x, ty = threadIdx.y;   // 32 x 8
    #pragma unroll
    for (int r = 0; r < 4; r++)
        t[ty + 8*r][tx] = W[(size_t)(k0 + ty + 8*r) * DMODEL + n0 + tx];
    __syncthreads();
    #pragma unroll
    for (int r = 0; r < 4; r++) {
        int row = ty + 8*r;
        float f = t[tx][row] * sc;
        __nv_bfloat16 h = __float2bfloat16_rn(f);
        __nv_bfloat16 l = __float2bfloat16_rn(f - __bfloat162float(h));
        size_t o = (size_t)(n0 + row) * DMODEL + k0 + tx;
        th[o] = h; tl[o] = l;
    }
}

__global__ __launch_bounds__(256) void bcat_kernel(
    const float* __restrict__ bq, const float* __restrict__ bk,
    const float* __restrict__ bv, float* __restrict__ o)
{
    int i = blockIdx.x * 256 + threadIdx.x;
    if (i >= NQKV) return;
    o[i] = (i < DMODEL) ? bq[i] * 0.125f
         : (i < 2*DMODEL) ? bk[i - DMODEL] : bv[i - 2*DMODEL];
}

// ---------------------------------------------------------------------------
// HMMA GEMM (R6/R8 config — frozen): CTA 128x64x64, 8 warps (4m x 2n),
// warp 32x32, cp.async 2-stage, 48KB stage -> 96KB dyn smem, 2 CTAs/SM.
// C = (Ah+Al)[M,768] @ (Bh+Bl)^T + bias; mode 0 fp32 / mode 1 bf16 hi+lo.
// ---------------------------------------------------------------------------
#define GST 49152
#define G_AH 0
#define G_AL 16384
#define G_BH 32768
#define G_BL 40960
#define NKC  (DMODEL/64)   // 12

__global__ __launch_bounds__(256) void gemm_hmma_kernel(
    const __nv_bfloat16* __restrict__ Ah, const __nv_bfloat16* __restrict__ Al,
    const __nv_bfloat16* __restrict__ Bh, const __nv_bfloat16* __restrict__ Bl,
    const float* __restrict__ bias, float* __restrict__ Cf,
    __nv_bfloat16* __restrict__ Oh, __nv_bfloat16* __restrict__ Ol,
    int mode, int ostride)
{
    extern __shared__ char smem[];
    const uint32_t sb = smem_u32(smem);
    const int tid  = threadIdx.x;
    const int lane = tid & 31, warp = tid >> 5;
    const int wm   = warp & 3, wn = warp >> 2;
    const int m0   = blockIdx.y * 128, n0 = blockIdx.x * 64;
    const int mw   = wm * 32, nw = wn * 32;

    auto prefetch = [&](int kc, int st) {
        const uint32_t base = sb + st * GST;
        #pragma unroll
        for (int r = 0; r < 4; r++) {
            int idx = tid + 256 * r;
            int row = idx >> 3, c16 = idx & 7;
            size_t g = (size_t)(m0 + row) * DMODEL + kc * 64 + c16 * 8;
            uint32_t off = SWZ128((uint32_t)(row * 128 + c16 * 16));
            cp16(base + G_AH + off, Ah + g);
            cp16(base + G_AL + off, Al + g);
        }
        #pragma unroll
        for (int r = 0; r < 2; r++) {
            int idx = tid + 256 * r;
            int row = idx >> 3, c16 = idx & 7;
            size_t g = (size_t)(n0 + row) * DMODEL + kc * 64 + c16 * 8;
            uint32_t off = SWZ128((uint32_t)(row * 128 + c16 * 16));
            cp16(base + G_BH + off, Bh + g);
            cp16(base + G_BL + off, Bl + g);
        }
        cp_commit();
    };

    float acc[2][4][4] = {};

    const int a_row = (lane & 15);
    const int a_col8 = (lane >> 4) * 8;
    const int b_row = ((lane >> 4) << 3) + (lane & 7);
    const int b_col8 = ((lane >> 3) & 1) * 8;

    prefetch(0, 0);

    for (int kc = 0; kc < NKC; kc++) {
        if (kc + 1 < NKC) { prefetch(kc + 1, (kc + 1) & 1); cp_wait<1>(); }
        else              { cp_wait<0>(); }
        __syncthreads();

        const uint32_t base = sb + (kc & 1) * GST;
        #pragma unroll
        for (int ks = 0; ks < 4; ks++) {
            const int ko = ks * 16;
            uint32_t ah[2][4], al[2][4], bh[2][4], bl[2][4];
            #pragma unroll
            for (int mi = 0; mi < 2; mi++) {
                uint32_t off = SWZ128((uint32_t)(
                    (mw + mi * 16 + a_row) * 128 + (ko + a_col8) * 2));
                ldsm_x4(ah[mi], base + G_AH + off);
                ldsm_x4(al[mi], base + G_AL + off);
            }
            #pragma unroll
            for (int hf = 0; hf < 2; hf++) {
                uint32_t off = SWZ128((uint32_t)(
                    (nw + hf * 16 + b_row) * 128 + (ko + b_col8) * 2));
                ldsm_x4(bh[hf], base + G_BH + off);
                ldsm_x4(bl[hf], base + G_BL + off);
            }
            #pragma unroll
            for (int mi = 0; mi < 2; mi++) {
                #pragma unroll
                for (int ni = 0; ni < 4; ni++) {
                    const uint32_t* bhf = &bh[ni >> 1][(ni & 1) * 2];
                    const uint32_t* blf = &bl[ni >> 1][(ni & 1) * 2];
                    mma_bf16(acc[mi][ni], ah[mi], bhf);
                    mma_bf16(acc[mi][ni], ah[mi], blf);
                    mma_bf16(acc[mi][ni], al[mi], bhf);
                }
            }
        }
        __syncthreads();
    }

    const int er = lane >> 2, ec = (lane & 3) * 2;
    #pragma unroll
    for (int mi = 0; mi < 2; mi++) {
        #pragma unroll
        for (int ni = 0; ni < 4; ni++) {
            int row = m0 + mw + mi * 16 + er;
            int col = n0 + nw + ni * 8 + ec;
            float2 b2 = *(const float2*)&bias[col];
            float v0 = acc[mi][ni][0] + b2.x, v1 = acc[mi][ni][1] + b2.y;
            float v2 = acc[mi][ni][2] + b2.x, v3 = acc[mi][ni][3] + b2.y;
            if (mode == 0) {
                *(float2*)&Cf[(size_t)row * ostride + col] = make_float2(v0, v1);
                *(float2*)&Cf[(size_t)(row + 8) * ostride + col] = make_float2(v2, v3);
            } else {
                uint32_t h0, l0, h1, l1;
                split2(v0, v1, h0, l0);
                split2(v2, v3, h1, l1);
                *(uint32_t*)&Oh[(size_t)row * ostride + col] = h0;
                *(uint32_t*)&Ol[(size_t)row * ostride + col] = l0;
                *(uint32_t*)&Oh[(size_t)(row + 8) * ostride + col] = h1;
                *(uint32_t*)&Ol[(size_t)(row + 8) * ostride + col] = l1;
            }
        }
    }
}

// ---------------------------------------------------------------------------
// Tensor-core causal flash attention (R9 config): 64 q-rows/CTA, 128 thr =
// 4 warps, cp.async double-buffered K/V, Q in own region, 2 CTAs/SM.
// Scale folded into q. Diagonal tile: warp w computes only key fragments
// nf2 <= w (S) and slices ks <= w (PV); rest fully masked / p == 0 (exact).
// ---------------------------------------------------------------------------
#define AQH 0
#define AQL 8192
#define ASTAGE 16384
#define ASTS 32768

__global__ __launch_bounds__(128, 2) void attn_tc_kernel(
    const __nv_bfloat16* __restrict__ qkvh, const __nv_bfloat16* __restrict__ qkvl,
    __nv_bfloat16* __restrict__ yh, __nv_bfloat16* __restrict__ yl)
{
    extern __shared__ char smem[];
    const uint32_t sb = smem_u32(smem);
    const int tid  = threadIdx.x;
    const int lane = tid & 31, warp = tid >> 5;     // warp 0..3
    const int qb   = gridDim.x - 1 - blockIdx.x;    // heavy blocks first
    const int bh_  = blockIdx.y;
    const int b    = bh_ / NH, h = bh_ % NH;
    const int q0   = qb * 64;
    const int mw   = warp * 16;

    const int a_row  = lane & 15;
    const int a_col8 = (lane >> 4) * 8;
    const int b_row  = ((lane >> 4) << 3) + (lane & 7);
    const int b_col8 = ((lane >> 3) & 1) * 8;
    const int er = lane >> 2, ec = (lane & 3) * 2;

    auto prefetchKV = [&](int kb, int st) {
        const uint32_t base = sb + ASTAGE + st * ASTS;
        const int k0 = kb * 64;
        #pragma unroll
        for (int r = 0; r < 4; r++) {
            int idx = tid + 128 * r;
            int row = idx >> 3, c16 = idx & 7;
            size_t gk = (size_t)((k0 + row) * BATCH + b) * NQKV + DMODEL + h * HD + c16 * 8;
            size_t gv = gk + DMODEL;
            uint32_t off = SWZ128((uint32_t)(row * 128 + c16 * 16));
            cp16(base + off,         qkvh + gk);
            cp16(base + 8192 + off,  qkvl + gk);
            cp16(base + 16384 + off, qkvh + gv);
            cp16(base + 24576 + off, qkvl + gv);
        }
        cp_commit();
    };

    // --- load Q tile (64 rows, hi/lo) into smem ---
    #pragma unroll
    for (int r = 0; r < 4; r++) {
        int idx = tid + 128 * r;
        int row = idx >> 3, c16 = idx & 7;
        size_t g = (size_t)((q0 + row) * BATCH + b) * NQKV + h * HD + c16 * 8;
        uint32_t off = SWZ128((uint32_t)(row * 128 + c16 * 16));
        *(uint4*)(smem + AQH + off) = *(const uint4*)&qkvh[g];
        *(uint4*)(smem + AQL + off) = *(const uint4*)&qkvl[g];
    }
    prefetchKV(0, 0);
    __syncthreads();

    // --- Q fragments (held all kernel) ---
    uint32_t aqh[4][4], aql[4][4];
    #pragma unroll
    for (int ks = 0; ks < 4; ks++) {
        uint32_t off = SWZ128((uint32_t)((mw + a_row) * 128 + (ks * 16 + a_col8) * 2));
        ldsm_x4(aqh[ks], sb + AQH + off);
        ldsm_x4(aql[ks], sb + AQL + off);
    }

    float o[8][4] = {};
    float m_[2] = {-1e30f, -1e30f};
    float l_[2] = {0.f, 0.f};

    const int ntiles = qb + 1;
    for (int kb = 0; kb < ntiles; kb++) {
        if (kb + 1 < ntiles) { prefetchKV(kb + 1, (kb + 1) & 1); cp_wait<1>(); }
        else                 { cp_wait<0>(); }
        __syncthreads();

        const int k0 = kb * 64;
        const bool diag = (kb == qb);
        const int frmax = diag ? (warp + 1) : 4;   // key fragments this warp needs
        const uint32_t base = sb + ASTAGE + (kb & 1) * ASTS;
        const uint32_t kH = base, kL = base + 8192, vH = base + 16384, vL = base + 24576;

        // --- S = Q @ K^T (3-MMA split); one K frag pair live at a time ---
        float s[8][4] = {};
        #pragma unroll
        for (int ks = 0; ks < 4; ks++) {
            #pragma unroll
            for (int nf2 = 0; nf2 < 4; nf2++) {
                if (nf2 >= frmax) break;
                uint32_t kh4[4], kl4[4];
                uint32_t off = SWZ128((uint32_t)(
                    (nf2 * 16 + b_row) * 128 + (ks * 16 + b_col8) * 2));
                ldsm_x4(kh4, kH + off);
                ldsm_x4(kl4, kL + off);
                mma_bf16(s[2*nf2],   aqh[ks], &kh4[0]);
                mma_bf16(s[2*nf2],   aqh[ks], &kl4[0]);
                mma_bf16(s[2*nf2],   aql[ks], &kh4[0]);
                mma_bf16(s[2*nf2+1], aqh[ks], &kh4[2]);
                mma_bf16(s[2*nf2+1], aqh[ks], &kl4[2]);
                mma_bf16(s[2*nf2+1], aql[ks], &kh4[2]);
            }
        }

        // --- causal mask (scale pre-folded into q); diagonal tiles only.
        //     Also sweeps skipped (zero-init) fragments to -inf. ---
        if (diag) {
            #pragma unroll
            for (int nf = 0; nf < 8; nf++) {
                #pragma unroll
                for (int c = 0; c < 4; c++) {
                    int key = k0 + nf * 8 + ec + (c & 1);
                    int qr  = q0 + mw + er + (c >> 1) * 8;
                    if (key > qr) s[nf][c] = -1e30f;
                }
            }
        }

        // --- online softmax ---
        float mx0 = -1e30f, mx1 = -1e30f;
        #pragma unroll
        for (int nf = 0; nf < 8; nf++) {
            mx0 = fmaxf(mx0, fmaxf(s[nf][0], s[nf][1]));
            mx1 = fmaxf(mx1, fmaxf(s[nf][2], s[nf][3]));
        }
        mx0 = fmaxf(mx0, __shfl_xor_sync(0xffffffffu, mx0, 1));
        mx0 = fmaxf(mx0, __shfl_xor_sync(0xffffffffu, mx0, 2));
        mx1 = fmaxf(mx1, __shfl_xor_sync(0xffffffffu, mx1, 1));
        mx1 = fmaxf(mx1, __shfl_xor_sync(0xffffffffu, mx1, 2));
        float mn0 = fmaxf(m_[0], mx0), mn1 = fmaxf(m_[1], mx1);
        float al0 = __expf(m_[0] - mn0), al1 = __expf(m_[1] - mn1);
        m_[0] = mn0; m_[1] = mn1;
        float sum0 = 0.f, sum1 = 0.f;
        #pragma unroll
        for (int nf = 0; nf < 8; nf++) {
            s[nf][0] = __expf(s[nf][0] - mn0); sum0 += s[nf][0];
            s[nf][1] = __expf(s[nf][1] - mn0); sum0 += s[nf][1];
            s[nf][2] = __expf(s[nf][2] - mn1); sum1 += s[nf][2];
            s[nf][3] = __expf(s[nf][3] - mn1); sum1 += s[nf][3];
        }
        sum0 += __shfl_xor_sync(0xffffffffu, sum0, 1);
        sum0 += __shfl_xor_sync(0xffffffffu, sum0, 2);
        sum1 += __shfl_xor_sync(0xffffffffu, sum1, 1);
        sum1 += __shfl_xor_sync(0xffffffffu, sum1, 2);
        l_[0] = l_[0] * al0 + sum0;
        l_[1] = l_[1] * al1 + sum1;
        #pragma unroll
        for (int df = 0; df < 8; df++) {
            o[df][0] *= al0; o[df][1] *= al0;
            o[df][2] *= al1; o[df][3] *= al1;
        }

        // --- O += P @ V (P split hi/lo; V^T via ldmatrix.trans).
        //     Diagonal: key slices ks > warp have p == 0 -> skipped (exact). ---
        #pragma unroll
        for (int ks = 0; ks < 4; ks++) {
            if (ks >= frmax) break;
            uint32_t aph[4], apl[4];
            split2(s[2*ks][0],   s[2*ks][1],   aph[0], apl[0]);
            split2(s[2*ks][2],   s[2*ks][3],   aph[1], apl[1]);
            split2(s[2*ks+1][0], s[2*ks+1][1], aph[2], apl[2]);
            split2(s[2*ks+1][2], s[2*ks+1][3], aph[3], apl[3]);
            #pragma unroll
            for (int df2 = 0; df2 < 4; df2++) {
                uint32_t off = SWZ128((uint32_t)(
                    (ks * 16 + a_row) * 128 + (df2 * 16 + a_col8) * 2));
                uint32_t tvh[4], tvl[4];
                ldsm_x4_t(tvh, vH + off);
                ldsm_x4_t(tvl, vL + off);
                mma_bf16(o[2*df2],   aph, &tvh[0]);
                mma_bf16(o[2*df2],   aph, &tvl[0]);
                mma_bf16(o[2*df2],   apl, &tvh[0]);
                mma_bf16(o[2*df2+1], aph, &tvh[2]);
                mma_bf16(o[2*df2+1], aph, &tvl[2]);
                mma_bf16(o[2*df2+1], apl, &tvh[2]);
            }
        }
        __syncthreads();
    }

    // --- epilogue: normalize, split, store bf16 hi/lo ---
    float inv0 = 1.f / l_[0], inv1 = 1.f / l_[1];
    int tok0 = (q0 + mw + er) * BATCH + b;
    int tok1 = tok0 + 8 * BATCH;
    #pragma unroll
    for (int df = 0; df < 8; df++) {
        int col = h * HD + df * 8 + ec;
        uint32_t h0, l0, h1, l1;
        split2(o[df][0] * inv0, o[df][1] * inv0, h0, l0);
        split2(o[df][2] * inv1, o[df][3] * inv1, h1, l1);
        *(uint32_t*)&yh[(size_t)tok0 * DMODEL + col] = h0;
        *(uint32_t*)&yl[(size_t)tok0 * DMODEL + col] = l0;
        *(uint32_t*)&yh[(size_t)tok1 * DMODEL + col] = h1;
        *(uint32_t*)&yl[(size_t)tok1 * DMODEL + col] = l1;
    }
}

// ---------------------------------------------------------------------------
extern "C" void kernel_launch(void* const* d_in, const int* in_sizes, int n_in,
                              void* d_out, int out_size)
{
    const float* x  = (const float*)d_in[0];
    const float* Wq = (const float*)d_in[1];
    const float* bq = (const float*)d_in[2];
    const float* Wk = (const float*)d_in[3];
    const float* bk = (const float*)d_in[4];
    const float* Wv = (const float*)d_in[5];
    const float* bv = (const float*)d_in[6];
    const float* Wo = (const float*)d_in[7];
    const float* bo = (const float*)d_in[8];
    float* out = (float*)d_out;

    __nv_bfloat16 *xs_hi, *xs_lo, *qkvh, *qkvl, *ys_hi, *ys_lo, *wt_hi, *wt_lo;
    float* bqkv;
    cudaGetSymbolAddress((void**)&xs_hi, g_xs_hi);
    cudaGetSymbolAddress((void**)&xs_lo, g_xs_lo);
    cudaGetSymbolAddress((void**)&qkvh, g_qkvh);
    cudaGetSymbolAddress((void**)&qkvl, g_qkvl);
    cudaGetSymbolAddress((void**)&ys_hi, g_ys_hi);
    cudaGetSymbolAddress((void**)&ys_lo, g_ys_lo);
    cudaGetSymbolAddress((void**)&wt_hi, g_wt_hi);
    cudaGetSymbolAddress((void**)&wt_lo, g_wt_lo);
    cudaGetSymbolAddress((void**)&bqkv, g_bqkv);

    static bool attr_set = false;
    if (!attr_set) {
        cudaFuncSetAttribute(gemm_hmma_kernel,
                             cudaFuncAttributeMaxDynamicSharedMemorySize, 2*GST);
        cudaFuncSetAttribute(attn_tc_kernel,
                             cudaFuncAttributeMaxDynamicSharedMemorySize, ASTAGE + 2*ASTS);
        attr_set = true;
    }

    const size_t WSZ = (size_t)DMODEL * DMODEL;

    dim3 wtGrid(DMODEL/32, DMODEL/32, 4), wtBlk(32, 8);
    wtsplit_kernel<<<wtGrid, wtBlk>>>(Wq, Wk, Wv, Wo, wt_hi, wt_lo);
    bcat_kernel<<<(NQKV + 255)/256, 256>>>(bq, bk, bv, bqkv);

    int n4 = NTOK * DMODEL / 4;
    fsplit_kernel<<<n4 / 256, 256>>>(x, xs_hi, xs_lo, n4);

    // Fused QKV projection: N = 2304
    dim3 qkvGrid(NQKV/64, NTOK/128);   // (36, 32) = 1152 CTAs
    gemm_hmma_kernel<<<qkvGrid, 256, 2*GST>>>(
        xs_hi, xs_lo, wt_hi, wt_lo, bqkv, nullptr, qkvh, qkvl, 1, NQKV);

    dim3 aGrid(NQB64, BATCH*NH);        // (32, 24) — fine-grained, heavy first
    attn_tc_kernel<<<aGrid, 128, ASTAGE + 2*ASTS>>>(qkvh, qkvl, ys_hi, ys_lo);

    dim3 oGrid(DMODEL/64, NTOK/128);    // (12, 32) = 384 CTAs
    gemm_hmma_kernel<<<oGrid, 256, 2*GST>>>(
        ys_hi, ys_lo, wt_hi + 3*WSZ, wt_lo + 3*WSZ, bo, out, nullptr, nullptr, 0, DMODEL);
}

// round 15
// speedup vs baseline: 1.0608x; 1.0608x over previous
#include <cuda_runtime.h>
#include <cuda_bf16.h>
#include <cstdint>
#include <math.h>

#define SEQ     2048
#define BATCH   2
#define DMODEL  768
#define NH      12
#define HD      64
#define NTOK    (SEQ*BATCH)   // 4096
#define NQKV    (3*DMODEL)    // 2304
#define NQB64   (SEQ/64)      // 32 q-blocks of 64 rows

// ---------------------------------------------------------------------------
// Scratch (__device__ globals; allocation-free rule)
// ---------------------------------------------------------------------------
__device__ __nv_bfloat16 g_xs_hi[NTOK*DMODEL];
__device__ __nv_bfloat16 g_xs_lo[NTOK*DMODEL];
__device__ __nv_bfloat16 g_qkvh[NTOK*NQKV];
__device__ __nv_bfloat16 g_qkvl[NTOK*NQKV];
__device__ __nv_bfloat16 g_ys_hi[NTOK*DMODEL];
__device__ __nv_bfloat16 g_ys_lo[NTOK*DMODEL];
__device__ __nv_bfloat16 g_wt_hi[4*DMODEL*DMODEL];   // transposed [N][K]; q,k,v,o slabs
__device__ __nv_bfloat16 g_wt_lo[4*DMODEL*DMODEL];
__device__ float g_bqkv[NQKV];

// ---------------------------------------------------------------------------
// Helpers (baseline PTX only — nothing sm_103a-gated)
// ---------------------------------------------------------------------------
__device__ __forceinline__ uint32_t smem_u32(const void* p) {
    uint32_t a;
    asm("{ .reg .u64 t; cvta.to.shared.u64 t, %1; cvt.u32.u64 %0, t; }" : "=r"(a) : "l"(p));
    return a;
}
#define SWZ128(o) ((o) ^ (((o) >> 3) & 0x70))

__device__ __forceinline__ void ldsm_x4(uint32_t* r, uint32_t addr) {
    asm volatile("ldmatrix.sync.aligned.m8n8.x4.shared.b16 {%0,%1,%2,%3}, [%4];"
        : "=r"(r[0]), "=r"(r[1]), "=r"(r[2]), "=r"(r[3]) : "r"(addr));
}
__device__ __forceinline__ void ldsm_x4_t(uint32_t* r, uint32_t addr) {
    asm volatile("ldmatrix.sync.aligned.m8n8.x4.trans.shared.b16 {%0,%1,%2,%3}, [%4];"
        : "=r"(r[0]), "=r"(r[1]), "=r"(r[2]), "=r"(r[3]) : "r"(addr));
}
__device__ __forceinline__ void mma_bf16(float* c, const uint32_t* a, const uint32_t* b) {
    asm volatile("mma.sync.aligned.m16n8k16.row.col.f32.bf16.bf16.f32 "
        "{%0,%1,%2,%3}, {%4,%5,%6,%7}, {%8,%9}, {%0,%1,%2,%3};"
        : "+f"(c[0]), "+f"(c[1]), "+f"(c[2]), "+f"(c[3])
        : "r"(a[0]), "r"(a[1]), "r"(a[2]), "r"(a[3]), "r"(b[0]), "r"(b[1]));
}
__device__ __forceinline__ float ex2(float x) {
    float r;
    asm("ex2.approx.f32 %0, %1;" : "=f"(r) : "f"(x));
    return r;
}
__device__ __forceinline__ void split2(float a, float b, uint32_t& hi, uint32_t& lo) {
    __nv_bfloat162 h = __floats2bfloat162_rn(a, b);
    __nv_bfloat162 l = __floats2bfloat162_rn(a - __bfloat162float(h.x),
                                             b - __bfloat162float(h.y));
    hi = *reinterpret_cast<uint32_t*>(&h);
    lo = *reinterpret_cast<uint32_t*>(&l);
}
__device__ __forceinline__ void cp16(uint32_t saddr, const void* g) {
    asm volatile("cp.async.cg.shared.global [%0], [%1], 16;" :: "r"(saddr), "l"(g) : "memory");
}
__device__ __forceinline__ void cp_commit() {
    asm volatile("cp.async.commit_group;" ::: "memory");
}
template<int N> __device__ __forceinline__ void cp_wait() {
    asm volatile("cp.async.wait_group %0;" :: "n"(N) : "memory");
}

// ---------------------------------------------------------------------------
// Conversion kernels
// ---------------------------------------------------------------------------
__global__ __launch_bounds__(256) void fsplit_kernel(
    const float* __restrict__ in, __nv_bfloat16* __restrict__ hi,
    __nv_bfloat16* __restrict__ lo, int n4)
{
    int i = (blockIdx.x * 256 + threadIdx.x) * 4;
    if (i >= n4 * 4) return;
    float4 f = *(const float4*)&in[i];
    uint32_t h0, l0, h1, l1;
    split2(f.x, f.y, h0, l0);
    split2(f.z, f.w, h1, l1);
    reinterpret_cast<uint32_t*>(hi + i)[0] = h0;
    reinterpret_cast<uint32_t*>(hi + i)[1] = h1;
    reinterpret_cast<uint32_t*>(lo + i)[0] = l0;
    reinterpret_cast<uint32_t*>(lo + i)[1] = l1;
}

// Scale folded into Wq: 0.125 * log2(e) so softmax can use raw ex2.
#define QSCALE 0.18033688011112042f

// All 4 weights in one launch: z picks W; W[K][N] -> out[n*768 + k] (B^T) hi/lo.
__global__ __launch_bounds__(256) void wtsplit_kernel(
    const float* __restrict__ W0, const float* __restrict__ W1,
    const float* __restrict__ W2, const float* __restrict__ W3,
    __nv_bfloat16* __restrict__ th_base, __nv_bfloat16* __restrict__ tl_base)
{
    const float* W = (blockIdx.z == 0) ? W0 : (blockIdx.z == 1) ? W1
                   : (blockIdx.z == 2) ? W2 : W3;
    const float sc = (blockIdx.z == 0) ? QSCALE : 1.0f;
    __nv_bfloat16* th = th_base + (size_t)blockIdx.z * DMODEL * DMODEL;
    __nv_bfloat16* tl = tl_base + (size_t)blockIdx.z * DMODEL * DMODEL;

    __shared__ float t[32][33];
    int n0 = blockIdx.x * 32, k0 = blockIdx.y * 32;
    int tx = threadIdx.x, ty = threadIdx.y;   // 32 x 8
    #pragma unroll
    for (int r = 0; r < 4; r++)
        t[ty + 8*r][tx] = W[(size_t)(k0 + ty + 8*r) * DMODEL + n0 + tx];
    __syncthreads();
    #pragma unroll
    for (int r = 0; r < 4; r++) {
        int row = ty + 8*r;
        float f = t[tx][row] * sc;
        __nv_bfloat16 h = __float2bfloat16_rn(f);
        __nv_bfloat16 l = __float2bfloat16_rn(f - __bfloat162float(h));
        size_t o = (size_t)(n0 + row) * DMODEL + k0 + tx;
        th[o] = h; tl[o] = l;
    }
}

__global__ __launch_bounds__(256) void bcat_kernel(
    const float* __restrict__ bq, const float* __restrict__ bk,
    const float* __restrict__ bv, float* __restrict__ o)
{
    int i = blockIdx.x * 256 + threadIdx.x;
    if (i >= NQKV) return;
    o[i] = (i < DMODEL) ? bq[i] * QSCALE
         : (i < 2*DMODEL) ? bk[i - DMODEL] : bv[i - 2*DMODEL];
}

// ---------------------------------------------------------------------------
// HMMA GEMM (R6/R8 config — frozen): CTA 128x64x64, 8 warps (4m x 2n),
// warp 32x32, cp.async 2-stage, 48KB stage -> 96KB dyn smem, 2 CTAs/SM.
// mode 0: fp32 out; mode 1: bf16 hi/lo out; mode 2: split-K over blockIdx.z
// (each z-slice does NKC/2 chunks, fp32 atomicAdd onto zeroed output,
//  bias added by the kc0==0 slice only — 2 commutative adds, deterministic).
// ---------------------------------------------------------------------------
#define GST 49152
#define G_AH 0
#define G_AL 16384
#define G_BH 32768
#define G_BL 40960
#define NKC  (DMODEL/64)   // 12

__global__ __launch_bounds__(256) void gemm_hmma_kernel(
    const __nv_bfloat16* __restrict__ Ah, const __nv_bfloat16* __restrict__ Al,
    const __nv_bfloat16* __restrict__ Bh, const __nv_bfloat16* __restrict__ Bl,
    const float* __restrict__ bias, float* __restrict__ Cf,
    __nv_bfloat16* __restrict__ Oh, __nv_bfloat16* __restrict__ Ol,
    int mode, int ostride)
{
    extern __shared__ char smem[];
    const uint32_t sb = smem_u32(smem);
    const int tid  = threadIdx.x;
    const int lane = tid & 31, warp = tid >> 5;
    const int wm   = warp & 3, wn = warp >> 2;
    const int m0   = blockIdx.y * 128, n0 = blockIdx.x * 64;
    const int mw   = wm * 32, nw = wn * 32;

    int kc0 = 0, kc1 = NKC;
    if (mode == 2) { kc0 = blockIdx.z * (NKC / 2); kc1 = kc0 + NKC / 2; }

    auto prefetch = [&](int kc, int st) {
        const uint32_t base = sb + st * GST;
        #pragma unroll
        for (int r = 0; r < 4; r++) {
            int idx = tid + 256 * r;
            int row = idx >> 3, c16 = idx & 7;
            size_t g = (size_t)(m0 + row) * DMODEL + kc * 64 + c16 * 8;
            uint32_t off = SWZ128((uint32_t)(row * 128 + c16 * 16));
            cp16(base + G_AH + off, Ah + g);
            cp16(base + G_AL + off, Al + g);
        }
        #pragma unroll
        for (int r = 0; r < 2; r++) {
            int idx = tid + 256 * r;
            int row = idx >> 3, c16 = idx & 7;
            size_t g = (size_t)(n0 + row) * DMODEL + kc * 64 + c16 * 8;
            uint32_t off = SWZ128((uint32_t)(row * 128 + c16 * 16));
            cp16(base + G_BH + off, Bh + g);
            cp16(base + G_BL + off, Bl + g);
        }
        cp_commit();
    };

    float acc[2][4][4] = {};

    const int a_row = (lane & 15);
    const int a_col8 = (lane >> 4) * 8;
    const int b_row = ((lane >> 4) << 3) + (lane & 7);
    const int b_col8 = ((lane >> 3) & 1) * 8;

    prefetch(kc0, kc0 & 1);

    for (int kc = kc0; kc < kc1; kc++) {
        if (kc + 1 < kc1) { prefetch(kc + 1, (kc + 1) & 1); cp_wait<1>(); }
        else              { cp_wait<0>(); }
        __syncthreads();

        const uint32_t base = sb + (kc & 1) * GST;
        #pragma unroll
        for (int ks = 0; ks < 4; ks++) {
            const int ko = ks * 16;
            uint32_t ah[2][4], al[2][4], bh[2][4], bl[2][4];
            #pragma unroll
            for (int mi = 0; mi < 2; mi++) {
                uint32_t off = SWZ128((uint32_t)(
                    (mw + mi * 16 + a_row) * 128 + (ko + a_col8) * 2));
                ldsm_x4(ah[mi], base + G_AH + off);
                ldsm_x4(al[mi], base + G_AL + off);
            }
            #pragma unroll
            for (int hf = 0; hf < 2; hf++) {
                uint32_t off = SWZ128((uint32_t)(
                    (nw + hf * 16 + b_row) * 128 + (ko + b_col8) * 2));
                ldsm_x4(bh[hf], base + G_BH + off);
                ldsm_x4(bl[hf], base + G_BL + off);
            }
            #pragma unroll
            for (int mi = 0; mi < 2; mi++) {
                #pragma unroll
                for (int ni = 0; ni < 4; ni++) {
                    const uint32_t* bhf = &bh[ni >> 1][(ni & 1) * 2];
                    const uint32_t* blf = &bl[ni >> 1][(ni & 1) * 2];
                    mma_bf16(acc[mi][ni], ah[mi], bhf);
                    mma_bf16(acc[mi][ni], ah[mi], blf);
                    mma_bf16(acc[mi][ni], al[mi], bhf);
                }
            }
        }
        __syncthreads();
    }

    const int er = lane >> 2, ec = (lane & 3) * 2;
    const bool addb = (kc0 == 0);
    #pragma unroll
    for (int mi = 0; mi < 2; mi++) {
        #pragma unroll
        for (int ni = 0; ni < 4; ni++) {
            int row = m0 + mw + mi * 16 + er;
            int col = n0 + nw + ni * 8 + ec;
            float2 b2 = *(const float2*)&bias[col];
            float bx = addb ? b2.x : 0.f, by = addb ? b2.y : 0.f;
            float v0 = acc[mi][ni][0] + bx, v1 = acc[mi][ni][1] + by;
            float v2 = acc[mi][ni][2] + bx, v3 = acc[mi][ni][3] + by;
            if (mode == 0) {
                *(float2*)&Cf[(size_t)row * ostride + col] = make_float2(v0, v1);
                *(float2*)&Cf[(size_t)(row + 8) * ostride + col] = make_float2(v2, v3);
            } else if (mode == 2) {
                atomicAdd(&Cf[(size_t)row * ostride + col],     v0);
                atomicAdd(&Cf[(size_t)row * ostride + col + 1], v1);
                atomicAdd(&Cf[(size_t)(row + 8) * ostride + col],     v2);
                atomicAdd(&Cf[(size_t)(row + 8) * ostride + col + 1], v3);
            } else {
                uint32_t h0, l0, h1, l1;
                split2(v0, v1, h0, l0);
                split2(v2, v3, h1, l1);
                *(uint32_t*)&Oh[(size_t)row * ostride + col] = h0;
                *(uint32_t*)&Ol[(size_t)row * ostride + col] = l0;
                *(uint32_t*)&Oh[(size_t)(row + 8) * ostride + col] = h1;
                *(uint32_t*)&Ol[(size_t)(row + 8) * ostride + col] = l1;
            }
        }
    }
}

// ---------------------------------------------------------------------------
// Tensor-core causal flash attention (R9 loop structure — straight-line,
// no skips): 64 q-rows/CTA, 128 thr = 4 warps, cp.async double-buffered K/V,
// 2 CTAs/SM. Scale*log2e folded into q; softmax uses raw ex2.
// ---------------------------------------------------------------------------
#define AQH 0
#define AQL 8192
#define ASTAGE 16384
#define ASTS 32768

__global__ __launch_bounds__(128, 2) void attn_tc_kernel(
    const __nv_bfloat16* __restrict__ qkvh, const __nv_bfloat16* __restrict__ qkvl,
    __nv_bfloat16* __restrict__ yh, __nv_bfloat16* __restrict__ yl)
{
    extern __shared__ char smem[];
    const uint32_t sb = smem_u32(smem);
    const int tid  = threadIdx.x;
    const int lane = tid & 31, warp = tid >> 5;     // warp 0..3
    const int qb   = gridDim.x - 1 - blockIdx.x;    // heavy blocks first
    const int bh_  = blockIdx.y;
    const int b    = bh_ / NH, h = bh_ % NH;
    const int q0   = qb * 64;
    const int mw   = warp * 16;

    const int a_row  = lane & 15;
    const int a_col8 = (lane >> 4) * 8;
    const int b_row  = ((lane >> 4) << 3) + (lane & 7);
    const int b_col8 = ((lane >> 3) & 1) * 8;
    const int er = lane >> 2, ec = (lane & 3) * 2;

    auto prefetchKV = [&](int kb, int st) {
        const uint32_t base = sb + ASTAGE + st * ASTS;
        const int k0 = kb * 64;
        #pragma unroll
        for (int r = 0; r < 4; r++) {
            int idx = tid + 128 * r;
            int row = idx >> 3, c16 = idx & 7;
            size_t gk = (size_t)((k0 + row) * BATCH + b) * NQKV + DMODEL + h * HD + c16 * 8;
            size_t gv = gk + DMODEL;
            uint32_t off = SWZ128((uint32_t)(row * 128 + c16 * 16));
            cp16(base + off,         qkvh + gk);
            cp16(base + 8192 + off,  qkvl + gk);
            cp16(base + 16384 + off, qkvh + gv);
            cp16(base + 24576 + off, qkvl + gv);
        }
        cp_commit();
    };

    // --- load Q tile (64 rows, hi/lo) into smem ---
    #pragma unroll
    for (int r = 0; r < 4; r++) {
        int idx = tid + 128 * r;
        int row = idx >> 3, c16 = idx & 7;
        size_t g = (size_t)((q0 + row) * BATCH + b) * NQKV + h * HD + c16 * 8;
        uint32_t off = SWZ128((uint32_t)(row * 128 + c16 * 16));
        *(uint4*)(smem + AQH + off) = *(const uint4*)&qkvh[g];
        *(uint4*)(smem + AQL + off) = *(const uint4*)&qkvl[g];
    }
    prefetchKV(0, 0);
    __syncthreads();

    // --- Q fragments (held all kernel) ---
    uint32_t aqh[4][4], aql[4][4];
    #pragma unroll
    for (int ks = 0; ks < 4; ks++) {
        uint32_t off = SWZ128((uint32_t)((mw + a_row) * 128 + (ks * 16 + a_col8) * 2));
        ldsm_x4(aqh[ks], sb + AQH + off);
        ldsm_x4(aql[ks], sb + AQL + off);
    }

    float o[8][4] = {};
    float m_[2] = {-1e30f, -1e30f};
    float l_[2] = {0.f, 0.f};

    const int ntiles = qb + 1;
    for (int kb = 0; kb < ntiles; kb++) {
        if (kb + 1 < ntiles) { prefetchKV(kb + 1, (kb + 1) & 1); cp_wait<1>(); }
        else                 { cp_wait<0>(); }
        __syncthreads();

        const int k0 = kb * 64;
        const uint32_t base = sb + ASTAGE + (kb & 1) * ASTS;
        const uint32_t kH = base, kL = base + 8192, vH = base + 16384, vL = base + 24576;

        // --- S = Q @ K^T (3-MMA split); one K frag pair live at a time ---
        float s[8][4] = {};
        #pragma unroll
        for (int ks = 0; ks < 4; ks++) {
            #pragma unroll
            for (int nf2 = 0; nf2 < 4; nf2++) {
                uint32_t kh4[4], kl4[4];
                uint32_t off = SWZ128((uint32_t)(
                    (nf2 * 16 + b_row) * 128 + (ks * 16 + b_col8) * 2));
                ldsm_x4(kh4, kH + off);
                ldsm_x4(kl4, kL + off);
                mma_bf16(s[2*nf2],   aqh[ks], &kh4[0]);
                mma_bf16(s[2*nf2],   aqh[ks], &kl4[0]);
                mma_bf16(s[2*nf2],   aql[ks], &kh4[0]);
                mma_bf16(s[2*nf2+1], aqh[ks], &kh4[2]);
                mma_bf16(s[2*nf2+1], aqh[ks], &kl4[2]);
                mma_bf16(s[2*nf2+1], aql[ks], &kh4[2]);
            }
        }

        // --- causal mask (scale pre-folded into q); diagonal tile only ---
        if (k0 + 63 > q0 + mw) {
            #pragma unroll
            for (int nf = 0; nf < 8; nf++) {
                #pragma unroll
                for (int c = 0; c < 4; c++) {
                    int key = k0 + nf * 8 + ec + (c & 1);
                    int qr  = q0 + mw + er + (c >> 1) * 8;
                    if (key > qr) s[nf][c] = -1e30f;
                }
            }
        }

        // --- online softmax (log2 domain; raw ex2) ---
        float mx0 = -1e30f, mx1 = -1e30f;
        #pragma unroll
        for (int nf = 0; nf < 8; nf++) {
            mx0 = fmaxf(mx0, fmaxf(s[nf][0], s[nf][1]));
            mx1 = fmaxf(mx1, fmaxf(s[nf][2], s[nf][3]));
        }
        mx0 = fmaxf(mx0, __shfl_xor_sync(0xffffffffu, mx0, 1));
        mx0 = fmaxf(mx0, __shfl_xor_sync(0xffffffffu, mx0, 2));
        mx1 = fmaxf(mx1, __shfl_xor_sync(0xffffffffu, mx1, 1));
        mx1 = fmaxf(mx1, __shfl_xor_sync(0xffffffffu, mx1, 2));
        float mn0 = fmaxf(m_[0], mx0), mn1 = fmaxf(m_[1], mx1);
        float al0 = ex2(m_[0] - mn0), al1 = ex2(m_[1] - mn1);
        m_[0] = mn0; m_[1] = mn1;
        float sum0 = 0.f, sum1 = 0.f;
        #pragma unroll
        for (int nf = 0; nf < 8; nf++) {
            s[nf][0] = ex2(s[nf][0] - mn0); sum0 += s[nf][0];
            s[nf][1] = ex2(s[nf][1] - mn0); sum0 += s[nf][1];
            s[nf][2] = ex2(s[nf][2] - mn1); sum1 += s[nf][2];
            s[nf][3] = ex2(s[nf][3] - mn1); sum1 += s[nf][3];
        }
        sum0 += __shfl_xor_sync(0xffffffffu, sum0, 1);
        sum0 += __shfl_xor_sync(0xffffffffu, sum0, 2);
        sum1 += __shfl_xor_sync(0xffffffffu, sum1, 1);
        sum1 += __shfl_xor_sync(0xffffffffu, sum1, 2);
        l_[0] = l_[0] * al0 + sum0;
        l_[1] = l_[1] * al1 + sum1;
        #pragma unroll
        for (int df = 0; df < 8; df++) {
            o[df][0] *= al0; o[df][1] *= al0;
            o[df][2] *= al1; o[df][3] *= al1;
        }

        // --- O += P @ V (P split hi/lo; V^T via ldmatrix.trans) ---
        #pragma unroll
        for (int ks = 0; ks < 4; ks++) {
            uint32_t aph[4], apl[4];
            split2(s[2*ks][0],   s[2*ks][1],   aph[0], apl[0]);
            split2(s[2*ks][2],   s[2*ks][3],   aph[1], apl[1]);
            split2(s[2*ks+1][0], s[2*ks+1][1], aph[2], apl[2]);
            split2(s[2*ks+1][2], s[2*ks+1][3], aph[3], apl[3]);
            #pragma unroll
            for (int df2 = 0; df2 < 4; df2++) {
                uint32_t off = SWZ128((uint32_t)(
                    (ks * 16 + a_row) * 128 + (df2 * 16 + a_col8) * 2));
                uint32_t tvh[4], tvl[4];
                ldsm_x4_t(tvh, vH + off);
                ldsm_x4_t(tvl, vL + off);
                mma_bf16(o[2*df2],   aph, &tvh[0]);
                mma_bf16(o[2*df2],   aph, &tvl[0]);
                mma_bf16(o[2*df2],   apl, &tvh[0]);
                mma_bf16(o[2*df2+1], aph, &tvh[2]);
                mma_bf16(o[2*df2+1], aph, &tvl[2]);
                mma_bf16(o[2*df2+1], apl, &tvh[2]);
            }
        }
        __syncthreads();
    }

    // --- epilogue: normalize, split, store bf16 hi/lo ---
    float inv0 = 1.f / l_[0], inv1 = 1.f / l_[1];
    int tok0 = (q0 + mw + er) * BATCH + b;
    int tok1 = tok0 + 8 * BATCH;
    #pragma unroll
    for (int df = 0; df < 8; df++) {
        int col = h * HD + df * 8 + ec;
        uint32_t h0, l0, h1, l1;
        split2(o[df][0] * inv0, o[df][1] * inv0, h0, l0);
        split2(o[df][2] * inv1, o[df][3] * inv1, h1, l1);
        *(uint32_t*)&yh[(size_t)tok0 * DMODEL + col] = h0;
        *(uint32_t*)&yl[(size_t)tok0 * DMODEL + col] = l0;
        *(uint32_t*)&yh[(size_t)tok1 * DMODEL + col] = h1;
        *(uint32_t*)&yl[(size_t)tok1 * DMODEL + col] = l1;
    }
}

// ---------------------------------------------------------------------------
extern "C" void kernel_launch(void* const* d_in, const int* in_sizes, int n_in,
                              void* d_out, int out_size)
{
    const float* x  = (const float*)d_in[0];
    const float* Wq = (const float*)d_in[1];
    const float* bq = (const float*)d_in[2];
    const float* Wk = (const float*)d_in[3];
    const float* bk = (const float*)d_in[4];
    const float* Wv = (const float*)d_in[5];
    const float* bv = (const float*)d_in[6];
    const float* Wo = (const float*)d_in[7];
    const float* bo = (const float*)d_in[8];
    float* out = (float*)d_out;

    __nv_bfloat16 *xs_hi, *xs_lo, *qkvh, *qkvl, *ys_hi, *ys_lo, *wt_hi, *wt_lo;
    float* bqkv;
    cudaGetSymbolAddress((void**)&xs_hi, g_xs_hi);
    cudaGetSymbolAddress((void**)&xs_lo, g_xs_lo);
    cudaGetSymbolAddress((void**)&qkvh, g_qkvh);
    cudaGetSymbolAddress((void**)&qkvl, g_qkvl);
    cudaGetSymbolAddress((void**)&ys_hi, g_ys_hi);
    cudaGetSymbolAddress((void**)&ys_lo, g_ys_lo);
    cudaGetSymbolAddress((void**)&wt_hi, g_wt_hi);
    cudaGetSymbolAddress((void**)&wt_lo, g_wt_lo);
    cudaGetSymbolAddress((void**)&bqkv, g_bqkv);

    static bool attr_set = false;
    if (!attr_set) {
        cudaFuncSetAttribute(gemm_hmma_kernel,
                             cudaFuncAttributeMaxDynamicSharedMemorySize, 2*GST);
        cudaFuncSetAttribute(attn_tc_kernel,
                             cudaFuncAttributeMaxDynamicSharedMemorySize, ASTAGE + 2*ASTS);
        attr_set = true;
    }

    const size_t WSZ = (size_t)DMODEL * DMODEL;

    dim3 wtGrid(DMODEL/32, DMODEL/32, 4), wtBlk(32, 8);
    wtsplit_kernel<<<wtGrid, wtBlk>>>(Wq, Wk, Wv, Wo, wt_hi, wt_lo);
    bcat_kernel<<<(NQKV + 255)/256, 256>>>(bq, bk, bv, bqkv);

    int n4 = NTOK * DMODEL / 4;
    fsplit_kernel<<<n4 / 256, 256>>>(x, xs_hi, xs_lo, n4);

    // Fused QKV projection: N = 2304
    dim3 qkvGrid(NQKV/64, NTOK/128);   // (36, 32) = 1152 CTAs
    gemm_hmma_kernel<<<qkvGrid, 256, 2*GST>>>(
        xs_hi, xs_lo, wt_hi, wt_lo, bqkv, nullptr, qkvh, qkvl, 1, NQKV);

    dim3 aGrid(NQB64, BATCH*NH);        // (32, 24) — fine-grained, heavy first
    attn_tc_kernel<<<aGrid, 128, ASTAGE + 2*ASTS>>>(qkvh, qkvl, ys_hi, ys_lo);

    // O-proj: 2-way split-K, atomicAdd onto zeroed out (deterministic: 2
    // commutative fp32 adds per element; bias added by kc0==0 slice only).
    cudaMemsetAsync(out, 0, (size_t)NTOK * DMODEL * sizeof(float));
    dim3 oGrid(DMODEL/64, NTOK/128, 2); // (12, 32, 2) = 768 CTAs
    gemm_hmma_kernel<<<oGrid, 256, 2*GST>>>(
        ys_hi, ys_lo, wt_hi + 3*WSZ, wt_lo + 3*WSZ, bo, out, nullptr, nullptr, 2, DMODEL);
}

// round 16
// speedup vs baseline: 1.0987x; 1.0358x over previous
#include <cuda_runtime.h>
#include <cuda_bf16.h>
#include <cstdint>
#include <math.h>

#define SEQ     2048
#define BATCH   2
#define DMODEL  768
#define NH      12
#define HD      64
#define NTOK    (SEQ*BATCH)   // 4096
#define NQKV    (3*DMODEL)    // 2304
#define NQB64   (SEQ/64)      // 32 q-blocks of 64 rows

// ---------------------------------------------------------------------------
// Scratch (__device__ globals; allocation-free rule)
// ---------------------------------------------------------------------------
__device__ __nv_bfloat16 g_xs_hi[NTOK*DMODEL];
__device__ __nv_bfloat16 g_xs_lo[NTOK*DMODEL];
__device__ __nv_bfloat16 g_qkvh[NTOK*NQKV];
__device__ __nv_bfloat16 g_qkvl[NTOK*NQKV];
__device__ __nv_bfloat16 g_ys_hi[NTOK*DMODEL];
__device__ __nv_bfloat16 g_ys_lo[NTOK*DMODEL];
__device__ __nv_bfloat16 g_wt_hi[4*DMODEL*DMODEL];   // transposed [N][K]; q,k,v,o slabs
__device__ __nv_bfloat16 g_wt_lo[4*DMODEL*DMODEL];
__device__ float g_bqkv[NQKV];

// ---------------------------------------------------------------------------
// Helpers (baseline PTX only — nothing sm_103a-gated)
// ---------------------------------------------------------------------------
__device__ __forceinline__ uint32_t smem_u32(const void* p) {
    uint32_t a;
    asm("{ .reg .u64 t; cvta.to.shared.u64 t, %1; cvt.u32.u64 %0, t; }" : "=r"(a) : "l"(p));
    return a;
}
#define SWZ128(o) ((o) ^ (((o) >> 3) & 0x70))

__device__ __forceinline__ void ldsm_x4(uint32_t* r, uint32_t addr) {
    asm volatile("ldmatrix.sync.aligned.m8n8.x4.shared.b16 {%0,%1,%2,%3}, [%4];"
        : "=r"(r[0]), "=r"(r[1]), "=r"(r[2]), "=r"(r[3]) : "r"(addr));
}
__device__ __forceinline__ void ldsm_x4_t(uint32_t* r, uint32_t addr) {
    asm volatile("ldmatrix.sync.aligned.m8n8.x4.trans.shared.b16 {%0,%1,%2,%3}, [%4];"
        : "=r"(r[0]), "=r"(r[1]), "=r"(r[2]), "=r"(r[3]) : "r"(addr));
}
__device__ __forceinline__ void mma_bf16(float* c, const uint32_t* a, const uint32_t* b) {
    asm volatile("mma.sync.aligned.m16n8k16.row.col.f32.bf16.bf16.f32 "
        "{%0,%1,%2,%3}, {%4,%5,%6,%7}, {%8,%9}, {%0,%1,%2,%3};"
        : "+f"(c[0]), "+f"(c[1]), "+f"(c[2]), "+f"(c[3])
        : "r"(a[0]), "r"(a[1]), "r"(a[2]), "r"(a[3]), "r"(b[0]), "r"(b[1]));
}
__device__ __forceinline__ float ex2(float x) {
    float r;
    asm("ex2.approx.f32 %0, %1;" : "=f"(r) : "f"(x));
    return r;
}
__device__ __forceinline__ void split2(float a, float b, uint32_t& hi, uint32_t& lo) {
    __nv_bfloat162 h = __floats2bfloat162_rn(a, b);
    __nv_bfloat162 l = __floats2bfloat162_rn(a - __bfloat162float(h.x),
                                             b - __bfloat162float(h.y));
    hi = *reinterpret_cast<uint32_t*>(&h);
    lo = *reinterpret_cast<uint32_t*>(&l);
}
__device__ __forceinline__ void cp16(uint32_t saddr, const void* g) {
    asm volatile("cp.async.cg.shared.global [%0], [%1], 16;" :: "r"(saddr), "l"(g) : "memory");
}
__device__ __forceinline__ void cp_commit() {
    asm volatile("cp.async.commit_group;" ::: "memory");
}
template<int N> __device__ __forceinline__ void cp_wait() {
    asm volatile("cp.async.wait_group %0;" :: "n"(N) : "memory");
}

// ---------------------------------------------------------------------------
// Conversion kernels
// ---------------------------------------------------------------------------
__global__ __launch_bounds__(256) void fsplit_kernel(
    const float* __restrict__ in, __nv_bfloat16* __restrict__ hi,
    __nv_bfloat16* __restrict__ lo, int n4)
{
    int i = (blockIdx.x * 256 + threadIdx.x) * 4;
    if (i >= n4 * 4) return;
    float4 f = *(const float4*)&in[i];
    uint32_t h0, l0, h1, l1;
    split2(f.x, f.y, h0, l0);
    split2(f.z, f.w, h1, l1);
    reinterpret_cast<uint32_t*>(hi + i)[0] = h0;
    reinterpret_cast<uint32_t*>(hi + i)[1] = h1;
    reinterpret_cast<uint32_t*>(lo + i)[0] = l0;
    reinterpret_cast<uint32_t*>(lo + i)[1] = l1;
}

// Scale folded into Wq: 0.125 * log2(e) so softmax can use raw ex2.
#define QSCALE 0.18033688011112042f

// All 4 weights in one launch: z picks W; W[K][N] -> out[n*768 + k] (B^T) hi/lo.
__global__ __launch_bounds__(256) void wtsplit_kernel(
    const float* __restrict__ W0, const float* __restrict__ W1,
    const float* __restrict__ W2, const float* __restrict__ W3,
    __nv_bfloat16* __restrict__ th_base, __nv_bfloat16* __restrict__ tl_base)
{
    const float* W = (blockIdx.z == 0) ? W0 : (blockIdx.z == 1) ? W1
                   : (blockIdx.z == 2) ? W2 : W3;
    const float sc = (blockIdx.z == 0) ? QSCALE : 1.0f;
    __nv_bfloat16* th = th_base + (size_t)blockIdx.z * DMODEL * DMODEL;
    __nv_bfloat16* tl = tl_base + (size_t)blockIdx.z * DMODEL * DMODEL;

    __shared__ float t[32][33];
    int n0 = blockIdx.x * 32, k0 = blockIdx.y * 32;
    int tx = threadIdx.x, ty = threadIdx.y;   // 32 x 8
    #pragma unroll
    for (int r = 0; r < 4; r++)
        t[ty + 8*r][tx] = W[(size_t)(k0 + ty + 8*r) * DMODEL + n0 + tx];
    __syncthreads();
    #pragma unroll
    for (int r = 0; r < 4; r++) {
        int row = ty + 8*r;
        float f = t[tx][row] * sc;
        __nv_bfloat16 h = __float2bfloat16_rn(f);
        __nv_bfloat16 l = __float2bfloat16_rn(f - __bfloat162float(h));
        size_t o = (size_t)(n0 + row) * DMODEL + k0 + tx;
        th[o] = h; tl[o] = l;
    }
}

__global__ __launch_bounds__(256) void bcat_kernel(
    const float* __restrict__ bq, const float* __restrict__ bk,
    const float* __restrict__ bv, float* __restrict__ o)
{
    int i = blockIdx.x * 256 + threadIdx.x;
    if (i >= NQKV) return;
    o[i] = (i < DMODEL) ? bq[i] * QSCALE
         : (i < 2*DMODEL) ? bk[i - DMODEL] : bv[i - 2*DMODEL];
}

// ---------------------------------------------------------------------------
// HMMA GEMM (R6/R8 config — frozen; compile-time bounds, modes 0/1 only):
// CTA 128x64x64, 8 warps (4m x 2n), warp 32x32, cp.async 2-stage,
// 48KB stage -> 96KB dyn smem, 2 CTAs/SM.
// C = (Ah+Al)[M,768] @ (Bh+Bl)^T + bias; mode 0 fp32 / mode 1 bf16 hi+lo.
// ---------------------------------------------------------------------------
#define GST 49152
#define G_AH 0
#define G_AL 16384
#define G_BH 32768
#define G_BL 40960
#define NKC  (DMODEL/64)   // 12

__global__ __launch_bounds__(256) void gemm_hmma_kernel(
    const __nv_bfloat16* __restrict__ Ah, const __nv_bfloat16* __restrict__ Al,
    const __nv_bfloat16* __restrict__ Bh, const __nv_bfloat16* __restrict__ Bl,
    const float* __restrict__ bias, float* __restrict__ Cf,
    __nv_bfloat16* __restrict__ Oh, __nv_bfloat16* __restrict__ Ol,
    int mode, int ostride)
{
    extern __shared__ char smem[];
    const uint32_t sb = smem_u32(smem);
    const int tid  = threadIdx.x;
    const int lane = tid & 31, warp = tid >> 5;
    const int wm   = warp & 3, wn = warp >> 2;
    const int m0   = blockIdx.y * 128, n0 = blockIdx.x * 64;
    const int mw   = wm * 32, nw = wn * 32;

    auto prefetch = [&](int kc, int st) {
        const uint32_t base = sb + st * GST;
        #pragma unroll
        for (int r = 0; r < 4; r++) {
            int idx = tid + 256 * r;
            int row = idx >> 3, c16 = idx & 7;
            size_t g = (size_t)(m0 + row) * DMODEL + kc * 64 + c16 * 8;
            uint32_t off = SWZ128((uint32_t)(row * 128 + c16 * 16));
            cp16(base + G_AH + off, Ah + g);
            cp16(base + G_AL + off, Al + g);
        }
        #pragma unroll
        for (int r = 0; r < 2; r++) {
            int idx = tid + 256 * r;
            int row = idx >> 3, c16 = idx & 7;
            size_t g = (size_t)(n0 + row) * DMODEL + kc * 64 + c16 * 8;
            uint32_t off = SWZ128((uint32_t)(row * 128 + c16 * 16));
            cp16(base + G_BH + off, Bh + g);
            cp16(base + G_BL + off, Bl + g);
        }
        cp_commit();
    };

    float acc[2][4][4] = {};

    const int a_row = (lane & 15);
    const int a_col8 = (lane >> 4) * 8;
    const int b_row = ((lane >> 4) << 3) + (lane & 7);
    const int b_col8 = ((lane >> 3) & 1) * 8;

    prefetch(0, 0);

    for (int kc = 0; kc < NKC; kc++) {
        if (kc + 1 < NKC) { prefetch(kc + 1, (kc + 1) & 1); cp_wait<1>(); }
        else              { cp_wait<0>(); }
        __syncthreads();

        const uint32_t base = sb + (kc & 1) * GST;
        #pragma unroll
        for (int ks = 0; ks < 4; ks++) {
            const int ko = ks * 16;
            uint32_t ah[2][4], al[2][4], bh[2][4], bl[2][4];
            #pragma unroll
            for (int mi = 0; mi < 2; mi++) {
                uint32_t off = SWZ128((uint32_t)(
                    (mw + mi * 16 + a_row) * 128 + (ko + a_col8) * 2));
                ldsm_x4(ah[mi], base + G_AH + off);
                ldsm_x4(al[mi], base + G_AL + off);
            }
            #pragma unroll
            for (int hf = 0; hf < 2; hf++) {
                uint32_t off = SWZ128((uint32_t)(
                    (nw + hf * 16 + b_row) * 128 + (ko + b_col8) * 2));
                ldsm_x4(bh[hf], base + G_BH + off);
                ldsm_x4(bl[hf], base + G_BL + off);
            }
            #pragma unroll
            for (int mi = 0; mi < 2; mi++) {
                #pragma unroll
                for (int ni = 0; ni < 4; ni++) {
                    const uint32_t* bhf = &bh[ni >> 1][(ni & 1) * 2];
                    const uint32_t* blf = &bl[ni >> 1][(ni & 1) * 2];
                    mma_bf16(acc[mi][ni], ah[mi], bhf);
                    mma_bf16(acc[mi][ni], ah[mi], blf);
                    mma_bf16(acc[mi][ni], al[mi], bhf);
                }
            }
        }
        __syncthreads();
    }

    const int er = lane >> 2, ec = (lane & 3) * 2;
    #pragma unroll
    for (int mi = 0; mi < 2; mi++) {
        #pragma unroll
        for (int ni = 0; ni < 4; ni++) {
            int row = m0 + mw + mi * 16 + er;
            int col = n0 + nw + ni * 8 + ec;
            float2 b2 = *(const float2*)&bias[col];
            float v0 = acc[mi][ni][0] + b2.x, v1 = acc[mi][ni][1] + b2.y;
            float v2 = acc[mi][ni][2] + b2.x, v3 = acc[mi][ni][3] + b2.y;
            if (mode == 0) {
                *(float2*)&Cf[(size_t)row * ostride + col] = make_float2(v0, v1);
                *(float2*)&Cf[(size_t)(row + 8) * ostride + col] = make_float2(v2, v3);
            } else {
                uint32_t h0, l0, h1, l1;
                split2(v0, v1, h0, l0);
                split2(v2, v3, h1, l1);
                *(uint32_t*)&Oh[(size_t)row * ostride + col] = h0;
                *(uint32_t*)&Ol[(size_t)row * ostride + col] = l0;
                *(uint32_t*)&Oh[(size_t)(row + 8) * ostride + col] = h1;
                *(uint32_t*)&Ol[(size_t)(row + 8) * ostride + col] = l1;
            }
        }
    }
}

// ---------------------------------------------------------------------------
// Tensor-core causal flash attention (R9 loop structure — straight-line):
// 64 q-rows/CTA, 128 thr = 4 warps, cp.async double-buffered K/V, 2 CTAs/SM.
// Scale*log2e folded into q; softmax uses raw ex2.
// ---------------------------------------------------------------------------
#define AQH 0
#define AQL 8192
#define ASTAGE 16384
#define ASTS 32768

__global__ __launch_bounds__(128, 2) void attn_tc_kernel(
    const __nv_bfloat16* __restrict__ qkvh, const __nv_bfloat16* __restrict__ qkvl,
    __nv_bfloat16* __restrict__ yh, __nv_bfloat16* __restrict__ yl)
{
    extern __shared__ char smem[];
    const uint32_t sb = smem_u32(smem);
    const int tid  = threadIdx.x;
    const int lane = tid & 31, warp = tid >> 5;     // warp 0..3
    const int qb   = gridDim.x - 1 - blockIdx.x;    // heavy blocks first
    const int bh_  = blockIdx.y;
    const int b    = bh_ / NH, h = bh_ % NH;
    const int q0   = qb * 64;
    const int mw   = warp * 16;

    const int a_row  = lane & 15;
    const int a_col8 = (lane >> 4) * 8;
    const int b_row  = ((lane >> 4) << 3) + (lane & 7);
    const int b_col8 = ((lane >> 3) & 1) * 8;
    const int er = lane >> 2, ec = (lane & 3) * 2;

    auto prefetchKV = [&](int kb, int st) {
        const uint32_t base = sb + ASTAGE + st * ASTS;
        const int k0 = kb * 64;
        #pragma unroll
        for (int r = 0; r < 4; r++) {
            int idx = tid + 128 * r;
            int row = idx >> 3, c16 = idx & 7;
            size_t gk = (size_t)((k0 + row) * BATCH + b) * NQKV + DMODEL + h * HD + c16 * 8;
            size_t gv = gk + DMODEL;
            uint32_t off = SWZ128((uint32_t)(row * 128 + c16 * 16));
            cp16(base + off,         qkvh + gk);
            cp16(base + 8192 + off,  qkvl + gk);
            cp16(base + 16384 + off, qkvh + gv);
            cp16(base + 24576 + off, qkvl + gv);
        }
        cp_commit();
    };

    // --- load Q tile (64 rows, hi/lo) into smem ---
    #pragma unroll
    for (int r = 0; r < 4; r++) {
        int idx = tid + 128 * r;
        int row = idx >> 3, c16 = idx & 7;
        size_t g = (size_t)((q0 + row) * BATCH + b) * NQKV + h * HD + c16 * 8;
        uint32_t off = SWZ128((uint32_t)(row * 128 + c16 * 16));
        *(uint4*)(smem + AQH + off) = *(const uint4*)&qkvh[g];
        *(uint4*)(smem + AQL + off) = *(const uint4*)&qkvl[g];
    }
    prefetchKV(0, 0);
    __syncthreads();

    // --- Q fragments (held all kernel) ---
    uint32_t aqh[4][4], aql[4][4];
    #pragma unroll
    for (int ks = 0; ks < 4; ks++) {
        uint32_t off = SWZ128((uint32_t)((mw + a_row) * 128 + (ks * 16 + a_col8) * 2));
        ldsm_x4(aqh[ks], sb + AQH + off);
        ldsm_x4(aql[ks], sb + AQL + off);
    }

    float o[8][4] = {};
    float m_[2] = {-1e30f, -1e30f};
    float l_[2] = {0.f, 0.f};

    const int ntiles = qb + 1;
    for (int kb = 0; kb < ntiles; kb++) {
        if (kb + 1 < ntiles) { prefetchKV(kb + 1, (kb + 1) & 1); cp_wait<1>(); }
        else                 { cp_wait<0>(); }
        __syncthreads();

        const int k0 = kb * 64;
        const uint32_t base = sb + ASTAGE + (kb & 1) * ASTS;
        const uint32_t kH = base, kL = base + 8192, vH = base + 16384, vL = base + 24576;

        // --- S = Q @ K^T (3-MMA split); one K frag pair live at a time ---
        float s[8][4] = {};
        #pragma unroll
        for (int ks = 0; ks < 4; ks++) {
            #pragma unroll
            for (int nf2 = 0; nf2 < 4; nf2++) {
                uint32_t kh4[4], kl4[4];
                uint32_t off = SWZ128((uint32_t)(
                    (nf2 * 16 + b_row) * 128 + (ks * 16 + b_col8) * 2));
                ldsm_x4(kh4, kH + off);
                ldsm_x4(kl4, kL + off);
                mma_bf16(s[2*nf2],   aqh[ks], &kh4[0]);
                mma_bf16(s[2*nf2],   aqh[ks], &kl4[0]);
                mma_bf16(s[2*nf2],   aql[ks], &kh4[0]);
                mma_bf16(s[2*nf2+1], aqh[ks], &kh4[2]);
                mma_bf16(s[2*nf2+1], aqh[ks], &kl4[2]);
                mma_bf16(s[2*nf2+1], aql[ks], &kh4[2]);
            }
        }

        // --- causal mask (scale pre-folded into q); diagonal tile only ---
        if (k0 + 63 > q0 + mw) {
            #pragma unroll
            for (int nf = 0; nf < 8; nf++) {
                #pragma unroll
                for (int c = 0; c < 4; c++) {
                    int key = k0 + nf * 8 + ec + (c & 1);
                    int qr  = q0 + mw + er + (c >> 1) * 8;
                    if (key > qr) s[nf][c] = -1e30f;
                }
            }
        }

        // --- online softmax (log2 domain; raw ex2) ---
        float mx0 = -1e30f, mx1 = -1e30f;
        #pragma unroll
        for (int nf = 0; nf < 8; nf++) {
            mx0 = fmaxf(mx0, fmaxf(s[nf][0], s[nf][1]));
            mx1 = fmaxf(mx1, fmaxf(s[nf][2], s[nf][3]));
        }
        mx0 = fmaxf(mx0, __shfl_xor_sync(0xffffffffu, mx0, 1));
        mx0 = fmaxf(mx0, __shfl_xor_sync(0xffffffffu, mx0, 2));
        mx1 = fmaxf(mx1, __shfl_xor_sync(0xffffffffu, mx1, 1));
        mx1 = fmaxf(mx1, __shfl_xor_sync(0xffffffffu, mx1, 2));
        float mn0 = fmaxf(m_[0], mx0), mn1 = fmaxf(m_[1], mx1);
        float al0 = ex2(m_[0] - mn0), al1 = ex2(m_[1] - mn1);
        m_[0] = mn0; m_[1] = mn1;
        float sum0 = 0.f, sum1 = 0.f;
        #pragma unroll
        for (int nf = 0; nf < 8; nf++) {
            s[nf][0] = ex2(s[nf][0] - mn0); sum0 += s[nf][0];
            s[nf][1] = ex2(s[nf][1] - mn0); sum0 += s[nf][1];
            s[nf][2] = ex2(s[nf][2] - mn1); sum1 += s[nf][2];
            s[nf][3] = ex2(s[nf][3] - mn1); sum1 += s[nf][3];
        }
        sum0 += __shfl_xor_sync(0xffffffffu, sum0, 1);
        sum0 += __shfl_xor_sync(0xffffffffu, sum0, 2);
        sum1 += __shfl_xor_sync(0xffffffffu, sum1, 1);
        sum1 += __shfl_xor_sync(0xffffffffu, sum1, 2);
        l_[0] = l_[0] * al0 + sum0;
        l_[1] = l_[1] * al1 + sum1;
        #pragma unroll
        for (int df = 0; df < 8; df++) {
            o[df][0] *= al0; o[df][1] *= al0;
            o[df][2] *= al1; o[df][3] *= al1;
        }

        // --- O += P @ V (P split hi/lo; V^T via ldmatrix.trans) ---
        #pragma unroll
        for (int ks = 0; ks < 4; ks++) {
            uint32_t aph[4], apl[4];
            split2(s[2*ks][0],   s[2*ks][1],   aph[0], apl[0]);
            split2(s[2*ks][2],   s[2*ks][3],   aph[1], apl[1]);
            split2(s[2*ks+1][0], s[2*ks+1][1], aph[2], apl[2]);
            split2(s[2*ks+1][2], s[2*ks+1][3], aph[3], apl[3]);
            #pragma unroll
            for (int df2 = 0; df2 < 4; df2++) {
                uint32_t off = SWZ128((uint32_t)(
                    (ks * 16 + a_row) * 128 + (df2 * 16 + a_col8) * 2));
                uint32_t tvh[4], tvl[4];
                ldsm_x4_t(tvh, vH + off);
                ldsm_x4_t(tvl, vL + off);
                mma_bf16(o[2*df2],   aph, &tvh[0]);
                mma_bf16(o[2*df2],   aph, &tvl[0]);
                mma_bf16(o[2*df2],   apl, &tvh[0]);
                mma_bf16(o[2*df2+1], aph, &tvh[2]);
                mma_bf16(o[2*df2+1], aph, &tvl[2]);
                mma_bf16(o[2*df2+1], apl, &tvh[2]);
            }
        }
        __syncthreads();
    }

    // --- epilogue: normalize, split, store bf16 hi/lo ---
    float inv0 = 1.f / l_[0], inv1 = 1.f / l_[1];
    int tok0 = (q0 + mw + er) * BATCH + b;
    int tok1 = tok0 + 8 * BATCH;
    #pragma unroll
    for (int df = 0; df < 8; df++) {
        int col = h * HD + df * 8 + ec;
        uint32_t h0, l0, h1, l1;
        split2(o[df][0] * inv0, o[df][1] * inv0, h0, l0);
        split2(o[df][2] * inv1, o[df][3] * inv1, h1, l1);
        *(uint32_t*)&yh[(size_t)tok0 * DMODEL + col] = h0;
        *(uint32_t*)&yl[(size_t)tok0 * DMODEL + col] = l0;
        *(uint32_t*)&yh[(size_t)tok1 * DMODEL + col] = h1;
        *(uint32_t*)&yl[(size_t)tok1 * DMODEL + col] = l1;
    }
}

// ---------------------------------------------------------------------------
extern "C" void kernel_launch(void* const* d_in, const int* in_sizes, int n_in,
                              void* d_out, int out_size)
{
    const float* x  = (const float*)d_in[0];
    const float* Wq = (const float*)d_in[1];
    const float* bq = (const float*)d_in[2];
    const float* Wk = (const float*)d_in[3];
    const float* bk = (const float*)d_in[4];
    const float* Wv = (const float*)d_in[5];
    const float* bv = (const float*)d_in[6];
    const float* Wo = (const float*)d_in[7];
    const float* bo = (const float*)d_in[8];
    float* out = (float*)d_out;

    __nv_bfloat16 *xs_hi, *xs_lo, *qkvh, *qkvl, *ys_hi, *ys_lo, *wt_hi, *wt_lo;
    float* bqkv;
    cudaGetSymbolAddress((void**)&xs_hi, g_xs_hi);
    cudaGetSymbolAddress((void**)&xs_lo, g_xs_lo);
    cudaGetSymbolAddress((void**)&qkvh, g_qkvh);
    cudaGetSymbolAddress((void**)&qkvl, g_qkvl);
    cudaGetSymbolAddress((void**)&ys_hi, g_ys_hi);
    cudaGetSymbolAddress((void**)&ys_lo, g_ys_lo);
    cudaGetSymbolAddress((void**)&wt_hi, g_wt_hi);
    cudaGetSymbolAddress((void**)&wt_lo, g_wt_lo);
    cudaGetSymbolAddress((void**)&bqkv, g_bqkv);

    static bool attr_set = false;
    if (!attr_set) {
        cudaFuncSetAttribute(gemm_hmma_kernel,
                             cudaFuncAttributeMaxDynamicSharedMemorySize, 2*GST);
        cudaFuncSetAttribute(attn_tc_kernel,
                             cudaFuncAttributeMaxDynamicSharedMemorySize, ASTAGE + 2*ASTS);
        attr_set = true;
    }

    const size_t WSZ = (size_t)DMODEL * DMODEL;

    dim3 wtGrid(DMODEL/32, DMODEL/32, 4), wtBlk(32, 8);
    wtsplit_kernel<<<wtGrid, wtBlk>>>(Wq, Wk, Wv, Wo, wt_hi, wt_lo);
    bcat_kernel<<<(NQKV + 255)/256, 256>>>(bq, bk, bv, bqkv);

    int n4 = NTOK * DMODEL / 4;
    fsplit_kernel<<<n4 / 256, 256>>>(x, xs_hi, xs_lo, n4);

    // Fused QKV projection: N = 2304
    dim3 qkvGrid(NQKV/64, NTOK/128);   // (36, 32) = 1152 CTAs
    gemm_hmma_kernel<<<qkvGrid, 256, 2*GST>>>(
        xs_hi, xs_lo, wt_hi, wt_lo, bqkv, nullptr, qkvh, qkvl, 1, NQKV);

    dim3 aGrid(NQB64, BATCH*NH);        // (32, 24) — fine-grained, heavy first
    attn_tc_kernel<<<aGrid, 128, ASTAGE + 2*ASTS>>>(qkvh, qkvl, ys_hi, ys_lo);

    dim3 oGrid(DMODEL/64, NTOK/128);    // (12, 32) = 384 CTAs
    gemm_hmma_kernel<<<oGrid, 256, 2*GST>>>(
        ys_hi, ys_lo, wt_hi + 3*WSZ, wt_lo + 3*WSZ, bo, out, nullptr, nullptr, 0, DMODEL);
}

// round 17
// speedup vs baseline: 1.1401x; 1.0377x over previous
#include <cuda_runtime.h>
#include <cuda_bf16.h>
#include <cstdint>
#include <math.h>

#define SEQ     2048
#define BATCH   2
#define DMODEL  768
#define NH      12
#define HD      64
#define NTOK    (SEQ*BATCH)   // 4096
#define NQKV    (3*DMODEL)    // 2304
#define NQB64   (SEQ/64)      // 32 q-blocks of 64 rows

// ---------------------------------------------------------------------------
// Scratch (__device__ globals; allocation-free rule)
// ---------------------------------------------------------------------------
__device__ __nv_bfloat16 g_xs_hi[NTOK*DMODEL];
__device__ __nv_bfloat16 g_xs_lo[NTOK*DMODEL];
__device__ __nv_bfloat16 g_qkvh[NTOK*NQKV];
__device__ __nv_bfloat16 g_qkvl[NTOK*NQKV];
__device__ __nv_bfloat16 g_ys_hi[NTOK*DMODEL];
__device__ __nv_bfloat16 g_ys_lo[NTOK*DMODEL];
__device__ __nv_bfloat16 g_wt_hi[4*DMODEL*DMODEL];   // transposed [N][K]; q,k,v,o slabs
__device__ __nv_bfloat16 g_wt_lo[4*DMODEL*DMODEL];
__device__ float g_bqkv[NQKV];

// ---------------------------------------------------------------------------
// Helpers (baseline PTX only — nothing sm_103a-gated)
// ---------------------------------------------------------------------------
__device__ __forceinline__ uint32_t smem_u32(const void* p) {
    uint32_t a;
    asm("{ .reg .u64 t; cvta.to.shared.u64 t, %1; cvt.u32.u64 %0, t; }" : "=r"(a) : "l"(p));
    return a;
}
#define SWZ128(o) ((o) ^ (((o) >> 3) & 0x70))

__device__ __forceinline__ void ldsm_x4(uint32_t* r, uint32_t addr) {
    asm volatile("ldmatrix.sync.aligned.m8n8.x4.shared.b16 {%0,%1,%2,%3}, [%4];"
        : "=r"(r[0]), "=r"(r[1]), "=r"(r[2]), "=r"(r[3]) : "r"(addr));
}
__device__ __forceinline__ void ldsm_x4_t(uint32_t* r, uint32_t addr) {
    asm volatile("ldmatrix.sync.aligned.m8n8.x4.trans.shared.b16 {%0,%1,%2,%3}, [%4];"
        : "=r"(r[0]), "=r"(r[1]), "=r"(r[2]), "=r"(r[3]) : "r"(addr));
}
__device__ __forceinline__ void mma_bf16(float* c, const uint32_t* a, const uint32_t* b) {
    asm volatile("mma.sync.aligned.m16n8k16.row.col.f32.bf16.bf16.f32 "
        "{%0,%1,%2,%3}, {%4,%5,%6,%7}, {%8,%9}, {%0,%1,%2,%3};"
        : "+f"(c[0]), "+f"(c[1]), "+f"(c[2]), "+f"(c[3])
        : "r"(a[0]), "r"(a[1]), "r"(a[2]), "r"(a[3]), "r"(b[0]), "r"(b[1]));
}
__device__ __forceinline__ float ex2(float x) {
    float r;
    asm("ex2.approx.f32 %0, %1;" : "=f"(r) : "f"(x));
    return r;
}
__device__ __forceinline__ void split2(float a, float b, uint32_t& hi, uint32_t& lo) {
    __nv_bfloat162 h = __floats2bfloat162_rn(a, b);
    __nv_bfloat162 l = __floats2bfloat162_rn(a - __bfloat162float(h.x),
                                             b - __bfloat162float(h.y));
    hi = *reinterpret_cast<uint32_t*>(&h);
    lo = *reinterpret_cast<uint32_t*>(&l);
}
__device__ __forceinline__ void cp16(uint32_t saddr, const void* g) {
    asm volatile("cp.async.cg.shared.global [%0], [%1], 16;" :: "r"(saddr), "l"(g) : "memory");
}
__device__ __forceinline__ void cp_commit() {
    asm volatile("cp.async.commit_group;" ::: "memory");
}
template<int N> __device__ __forceinline__ void cp_wait() {
    asm volatile("cp.async.wait_group %0;" :: "n"(N) : "memory");
}

// ---------------------------------------------------------------------------
// Conversion kernels
// ---------------------------------------------------------------------------
__global__ __launch_bounds__(256) void fsplit_kernel(
    const float* __restrict__ in, __nv_bfloat16* __restrict__ hi,
    __nv_bfloat16* __restrict__ lo, int n4)
{
    int i = (blockIdx.x * 256 + threadIdx.x) * 4;
    if (i >= n4 * 4) return;
    float4 f = *(const float4*)&in[i];
    uint32_t h0, l0, h1, l1;
    split2(f.x, f.y, h0, l0);
    split2(f.z, f.w, h1, l1);
    reinterpret_cast<uint32_t*>(hi + i)[0] = h0;
    reinterpret_cast<uint32_t*>(hi + i)[1] = h1;
    reinterpret_cast<uint32_t*>(lo + i)[0] = l0;
    reinterpret_cast<uint32_t*>(lo + i)[1] = l1;
}

// Scale folded into Wq: 0.125 * log2(e) so softmax can use raw ex2.
#define QSCALE 0.18033688011112042f

// All 4 weights in one launch: z picks W; W[K][N] -> out[n*768 + k] (B^T) hi/lo.
__global__ __launch_bounds__(256) void wtsplit_kernel(
    const float* __restrict__ W0, const float* __restrict__ W1,
    const float* __restrict__ W2, const float* __restrict__ W3,
    __nv_bfloat16* __restrict__ th_base, __nv_bfloat16* __restrict__ tl_base)
{
    const float* W = (blockIdx.z == 0) ? W0 : (blockIdx.z == 1) ? W1
                   : (blockIdx.z == 2) ? W2 : W3;
    const float sc = (blockIdx.z == 0) ? QSCALE : 1.0f;
    __nv_bfloat16* th = th_base + (size_t)blockIdx.z * DMODEL * DMODEL;
    __nv_bfloat16* tl = tl_base + (size_t)blockIdx.z * DMODEL * DMODEL;

    __shared__ float t[32][33];
    int n0 = blockIdx.x * 32, k0 = blockIdx.y * 32;
    int tx = threadIdx.x, ty = threadIdx.y;   // 32 x 8
    #pragma unroll
    for (int r = 0; r < 4; r++)
        t[ty + 8*r][tx] = W[(size_t)(k0 + ty + 8*r) * DMODEL + n0 + tx];
    __syncthreads();
    #pragma unroll
    for (int r = 0; r < 4; r++) {
        int row = ty + 8*r;
        float f = t[tx][row] * sc;
        __nv_bfloat16 h = __float2bfloat16_rn(f);
        __nv_bfloat16 l = __float2bfloat16_rn(f - __bfloat162float(h));
        size_t o = (size_t)(n0 + row) * DMODEL + k0 + tx;
        th[o] = h; tl[o] = l;
    }
}

__global__ __launch_bounds__(256) void bcat_kernel(
    const float* __restrict__ bq, const float* __restrict__ bk,
    const float* __restrict__ bv, float* __restrict__ o)
{
    int i = blockIdx.x * 256 + threadIdx.x;
    if (i >= NQKV) return;
    o[i] = (i < DMODEL) ? bq[i] * QSCALE
         : (i < 2*DMODEL) ? bk[i - DMODEL] : bv[i - 2*DMODEL];
}

// ---------------------------------------------------------------------------
// HMMA GEMM (R6/R8 config — frozen): CTA 128x64x64, 8 warps (4m x 2n),
// warp 32x32, cp.async 2-stage, 48KB stage -> 96KB dyn smem, 2 CTAs/SM.
// C = (Ah+Al)[M,768] @ (Bh+Bl)^T + bias; mode 0 fp32 / mode 1 bf16 hi+lo.
// ---------------------------------------------------------------------------
#define GST 49152
#define G_AH 0
#define G_AL 16384
#define G_BH 32768
#define G_BL 40960
#define NKC  (DMODEL/64)   // 12

__global__ __launch_bounds__(256) void gemm_hmma_kernel(
    const __nv_bfloat16* __restrict__ Ah, const __nv_bfloat16* __restrict__ Al,
    const __nv_bfloat16* __restrict__ Bh, const __nv_bfloat16* __restrict__ Bl,
    const float* __restrict__ bias, float* __restrict__ Cf,
    __nv_bfloat16* __restrict__ Oh, __nv_bfloat16* __restrict__ Ol,
    int mode, int ostride)
{
    extern __shared__ char smem[];
    const uint32_t sb = smem_u32(smem);
    const int tid  = threadIdx.x;
    const int lane = tid & 31, warp = tid >> 5;
    const int wm   = warp & 3, wn = warp >> 2;
    const int m0   = blockIdx.y * 128, n0 = blockIdx.x * 64;
    const int mw   = wm * 32, nw = wn * 32;

    auto prefetch = [&](int kc, int st) {
        const uint32_t base = sb + st * GST;
        #pragma unroll
        for (int r = 0; r < 4; r++) {
            int idx = tid + 256 * r;
            int row = idx >> 3, c16 = idx & 7;
            size_t g = (size_t)(m0 + row) * DMODEL + kc * 64 + c16 * 8;
            uint32_t off = SWZ128((uint32_t)(row * 128 + c16 * 16));
            cp16(base + G_AH + off, Ah + g);
            cp16(base + G_AL + off, Al + g);
        }
        #pragma unroll
        for (int r = 0; r < 2; r++) {
            int idx = tid + 256 * r;
            int row = idx >> 3, c16 = idx & 7;
            size_t g = (size_t)(n0 + row) * DMODEL + kc * 64 + c16 * 8;
            uint32_t off = SWZ128((uint32_t)(row * 128 + c16 * 16));
            cp16(base + G_BH + off, Bh + g);
            cp16(base + G_BL + off, Bl + g);
        }
        cp_commit();
    };

    float acc[2][4][4] = {};

    const int a_row = (lane & 15);
    const int a_col8 = (lane >> 4) * 8;
    const int b_row = ((lane >> 4) << 3) + (lane & 7);
    const int b_col8 = ((lane >> 3) & 1) * 8;

    prefetch(0, 0);

    for (int kc = 0; kc < NKC; kc++) {
        if (kc + 1 < NKC) { prefetch(kc + 1, (kc + 1) & 1); cp_wait<1>(); }
        else              { cp_wait<0>(); }
        __syncthreads();

        const uint32_t base = sb + (kc & 1) * GST;
        #pragma unroll
        for (int ks = 0; ks < 4; ks++) {
            const int ko = ks * 16;
            uint32_t ah[2][4], al[2][4], bh[2][4], bl[2][4];
            #pragma unroll
            for (int mi = 0; mi < 2; mi++) {
                uint32_t off = SWZ128((uint32_t)(
                    (mw + mi * 16 + a_row) * 128 + (ko + a_col8) * 2));
                ldsm_x4(ah[mi], base + G_AH + off);
                ldsm_x4(al[mi], base + G_AL + off);
            }
            #pragma unroll
            for (int hf = 0; hf < 2; hf++) {
                uint32_t off = SWZ128((uint32_t)(
                    (nw + hf * 16 + b_row) * 128 + (ko + b_col8) * 2));
                ldsm_x4(bh[hf], base + G_BH + off);
                ldsm_x4(bl[hf], base + G_BL + off);
            }
            #pragma unroll
            for (int mi = 0; mi < 2; mi++) {
                #pragma unroll
                for (int ni = 0; ni < 4; ni++) {
                    const uint32_t* bhf = &bh[ni >> 1][(ni & 1) * 2];
                    const uint32_t* blf = &bl[ni >> 1][(ni & 1) * 2];
                    mma_bf16(acc[mi][ni], ah[mi], bhf);
                    mma_bf16(acc[mi][ni], ah[mi], blf);
                    mma_bf16(acc[mi][ni], al[mi], bhf);
                }
            }
        }
        __syncthreads();
    }

    const int er = lane >> 2, ec = (lane & 3) * 2;
    #pragma unroll
    for (int mi = 0; mi < 2; mi++) {
        #pragma unroll
        for (int ni = 0; ni < 4; ni++) {
            int row = m0 + mw + mi * 16 + er;
            int col = n0 + nw + ni * 8 + ec;
            float2 b2 = *(const float2*)&bias[col];
            float v0 = acc[mi][ni][0] + b2.x, v1 = acc[mi][ni][1] + b2.y;
            float v2 = acc[mi][ni][2] + b2.x, v3 = acc[mi][ni][3] + b2.y;
            if (mode == 0) {
                *(float2*)&Cf[(size_t)row * ostride + col] = make_float2(v0, v1);
                *(float2*)&Cf[(size_t)(row + 8) * ostride + col] = make_float2(v2, v3);
            } else {
                uint32_t h0, l0, h1, l1;
                split2(v0, v1, h0, l0);
                split2(v2, v3, h1, l1);
                *(uint32_t*)&Oh[(size_t)row * ostride + col] = h0;
                *(uint32_t*)&Ol[(size_t)row * ostride + col] = l0;
                *(uint32_t*)&Oh[(size_t)(row + 8) * ostride + col] = h1;
                *(uint32_t*)&Ol[(size_t)(row + 8) * ostride + col] = l1;
            }
        }
    }
}

// ---------------------------------------------------------------------------
// Tensor-core causal flash attention: 64 q-rows/CTA, 128 thr = 4 warps,
// cp.async double-buffered K/V. Q kept hi-only (2-MMA S split: QhKh + QhKl;
// QlKh dropped — error ~2^-9 of score, well under tolerance). smem 72KB ->
// up to 3 CTAs/SM if regs allow. Scale*log2e folded into q; raw ex2 softmax.
// ---------------------------------------------------------------------------
#define AQH 0
#define ASTAGE 8192
#define ASTS 32768

__global__ __launch_bounds__(128, 2) void attn_tc_kernel(
    const __nv_bfloat16* __restrict__ qkvh, const __nv_bfloat16* __restrict__ qkvl,
    __nv_bfloat16* __restrict__ yh, __nv_bfloat16* __restrict__ yl)
{
    extern __shared__ char smem[];
    const uint32_t sb = smem_u32(smem);
    const int tid  = threadIdx.x;
    const int lane = tid & 31, warp = tid >> 5;     // warp 0..3
    const int qb   = gridDim.x - 1 - blockIdx.x;    // heavy blocks first
    const int bh_  = blockIdx.y;
    const int b    = bh_ / NH, h = bh_ % NH;
    const int q0   = qb * 64;
    const int mw   = warp * 16;

    const int a_row  = lane & 15;
    const int a_col8 = (lane >> 4) * 8;
    const int b_row  = ((lane >> 4) << 3) + (lane & 7);
    const int b_col8 = ((lane >> 3) & 1) * 8;
    const int er = lane >> 2, ec = (lane & 3) * 2;

    auto prefetchKV = [&](int kb, int st) {
        const uint32_t base = sb + ASTAGE + st * ASTS;
        const int k0 = kb * 64;
        #pragma unroll
        for (int r = 0; r < 4; r++) {
            int idx = tid + 128 * r;
            int row = idx >> 3, c16 = idx & 7;
            size_t gk = (size_t)((k0 + row) * BATCH + b) * NQKV + DMODEL + h * HD + c16 * 8;
            size_t gv = gk + DMODEL;
            uint32_t off = SWZ128((uint32_t)(row * 128 + c16 * 16));
            cp16(base + off,         qkvh + gk);
            cp16(base + 8192 + off,  qkvl + gk);
            cp16(base + 16384 + off, qkvh + gv);
            cp16(base + 24576 + off, qkvl + gv);
        }
        cp_commit();
    };

    // --- load Q tile (64 rows, hi only) into smem ---
    #pragma unroll
    for (int r = 0; r < 4; r++) {
        int idx = tid + 128 * r;
        int row = idx >> 3, c16 = idx & 7;
        size_t g = (size_t)((q0 + row) * BATCH + b) * NQKV + h * HD + c16 * 8;
        uint32_t off = SWZ128((uint32_t)(row * 128 + c16 * 16));
        *(uint4*)(smem + AQH + off) = *(const uint4*)&qkvh[g];
    }
    prefetchKV(0, 0);
    __syncthreads();

    // --- Q fragments (hi only, held all kernel) ---
    uint32_t aqh[4][4];
    #pragma unroll
    for (int ks = 0; ks < 4; ks++) {
        uint32_t off = SWZ128((uint32_t)((mw + a_row) * 128 + (ks * 16 + a_col8) * 2));
        ldsm_x4(aqh[ks], sb + AQH + off);
    }

    float o[8][4] = {};
    float m_[2] = {-1e30f, -1e30f};
    float l_[2] = {0.f, 0.f};

    const int ntiles = qb + 1;
    for (int kb = 0; kb < ntiles; kb++) {
        if (kb + 1 < ntiles) { prefetchKV(kb + 1, (kb + 1) & 1); cp_wait<1>(); }
        else                 { cp_wait<0>(); }
        __syncthreads();

        const int k0 = kb * 64;
        const uint32_t base = sb + ASTAGE + (kb & 1) * ASTS;
        const uint32_t kH = base, kL = base + 8192, vH = base + 16384, vL = base + 24576;

        // --- S = Qh @ (Kh + Kl)^T (2-MMA split) ---
        float s[8][4] = {};
        #pragma unroll
        for (int ks = 0; ks < 4; ks++) {
            #pragma unroll
            for (int nf2 = 0; nf2 < 4; nf2++) {
                uint32_t kh4[4], kl4[4];
                uint32_t off = SWZ128((uint32_t)(
                    (nf2 * 16 + b_row) * 128 + (ks * 16 + b_col8) * 2));
                ldsm_x4(kh4, kH + off);
                ldsm_x4(kl4, kL + off);
                mma_bf16(s[2*nf2],   aqh[ks], &kh4[0]);
                mma_bf16(s[2*nf2],   aqh[ks], &kl4[0]);
                mma_bf16(s[2*nf2+1], aqh[ks], &kh4[2]);
                mma_bf16(s[2*nf2+1], aqh[ks], &kl4[2]);
            }
        }

        // --- causal mask (scale pre-folded into q); diagonal tile only ---
        if (k0 + 63 > q0 + mw) {
            #pragma unroll
            for (int nf = 0; nf < 8; nf++) {
                #pragma unroll
                for (int c = 0; c < 4; c++) {
                    int key = k0 + nf * 8 + ec + (c & 1);
                    int qr  = q0 + mw + er + (c >> 1) * 8;
                    if (key > qr) s[nf][c] = -1e30f;
                }
            }
        }

        // --- online softmax (log2 domain; raw ex2) ---
        float mx0 = -1e30f, mx1 = -1e30f;
        #pragma unroll
        for (int nf = 0; nf < 8; nf++) {
            mx0 = fmaxf(mx0, fmaxf(s[nf][0], s[nf][1]));
            mx1 = fmaxf(mx1, fmaxf(s[nf][2], s[nf][3]));
        }
        mx0 = fmaxf(mx0, __shfl_xor_sync(0xffffffffu, mx0, 1));
        mx0 = fmaxf(mx0, __shfl_xor_sync(0xffffffffu, mx0, 2));
        mx1 = fmaxf(mx1, __shfl_xor_sync(0xffffffffu, mx1, 1));
        mx1 = fmaxf(mx1, __shfl_xor_sync(0xffffffffu, mx1, 2));
        float mn0 = fmaxf(m_[0], mx0), mn1 = fmaxf(m_[1], mx1);
        float al0 = ex2(m_[0] - mn0), al1 = ex2(m_[1] - mn1);
        m_[0] = mn0; m_[1] = mn1;
        float sum0 = 0.f, sum1 = 0.f;
        #pragma unroll
        for (int nf = 0; nf < 8; nf++) {
            s[nf][0] = ex2(s[nf][0] - mn0); sum0 += s[nf][0];
            s[nf][1] = ex2(s[nf][1] - mn0); sum0 += s[nf][1];
            s[nf][2] = ex2(s[nf][2] - mn1); sum1 += s[nf][2];
            s[nf][3] = ex2(s[nf][3] - mn1); sum1 += s[nf][3];
        }
        sum0 += __shfl_xor_sync(0xffffffffu, sum0, 1);
        sum0 += __shfl_xor_sync(0xffffffffu, sum0, 2);
        sum1 += __shfl_xor_sync(0xffffffffu, sum1, 1);
        sum1 += __shfl_xor_sync(0xffffffffu, sum1, 2);
        l_[0] = l_[0] * al0 + sum0;
        l_[1] = l_[1] * al1 + sum1;
        #pragma unroll
        for (int df = 0; df < 8; df++) {
            o[df][0] *= al0; o[df][1] *= al0;
            o[df][2] *= al1; o[df][3] *= al1;
        }

        // --- O += P @ V (P split hi/lo; V^T via ldmatrix.trans) ---
        #pragma unroll
        for (int ks = 0; ks < 4; ks++) {
            uint32_t aph[4], apl[4];
            split2(s[2*ks][0],   s[2*ks][1],   aph[0], apl[0]);
            split2(s[2*ks][2],   s[2*ks][3],   aph[1], apl[1]);
            split2(s[2*ks+1][0], s[2*ks+1][1], aph[2], apl[2]);
            split2(s[2*ks+1][2], s[2*ks+1][3], aph[3], apl[3]);
            #pragma unroll
            for (int df2 = 0; df2 < 4; df2++) {
                uint32_t off = SWZ128((uint32_t)(
                    (ks * 16 + a_row) * 128 + (df2 * 16 + a_col8) * 2));
                uint32_t tvh[4], tvl[4];
                ldsm_x4_t(tvh, vH + off);
                ldsm_x4_t(tvl, vL + off);
                mma_bf16(o[2*df2],   aph, &tvh[0]);
                mma_bf16(o[2*df2],   aph, &tvl[0]);
                mma_bf16(o[2*df2],   apl, &tvh[0]);
                mma_bf16(o[2*df2+1], aph, &tvh[2]);
                mma_bf16(o[2*df2+1], aph, &tvl[2]);
                mma_bf16(o[2*df2+1], apl, &tvh[2]);
            }
        }
        __syncthreads();
    }

    // --- epilogue: normalize, split, store bf16 hi/lo ---
    float inv0 = 1.f / l_[0], inv1 = 1.f / l_[1];
    int tok0 = (q0 + mw + er) * BATCH + b;
    int tok1 = tok0 + 8 * BATCH;
    #pragma unroll
    for (int df = 0; df < 8; df++) {
        int col = h * HD + df * 8 + ec;
        uint32_t h0, l0, h1, l1;
        split2(o[df][0] * inv0, o[df][1] * inv0, h0, l0);
        split2(o[df][2] * inv1, o[df][3] * inv1, h1, l1);
        *(uint32_t*)&yh[(size_t)tok0 * DMODEL + col] = h0;
        *(uint32_t*)&yl[(size_t)tok0 * DMODEL + col] = l0;
        *(uint32_t*)&yh[(size_t)tok1 * DMODEL + col] = h1;
        *(uint32_t*)&yl[(size_t)tok1 * DMODEL + col] = l1;
    }
}

// ---------------------------------------------------------------------------
extern "C" void kernel_launch(void* const* d_in, const int* in_sizes, int n_in,
                              void* d_out, int out_size)
{
    const float* x  = (const float*)d_in[0];
    const float* Wq = (const float*)d_in[1];
    const float* bq = (const float*)d_in[2];
    const float* Wk = (const float*)d_in[3];
    const float* bk = (const float*)d_in[4];
    const float* Wv = (const float*)d_in[5];
    const float* bv = (const float*)d_in[6];
    const float* Wo = (const float*)d_in[7];
    const float* bo = (const float*)d_in[8];
    float* out = (float*)d_out;

    __nv_bfloat16 *xs_hi, *xs_lo, *qkvh, *qkvl, *ys_hi, *ys_lo, *wt_hi, *wt_lo;
    float* bqkv;
    cudaGetSymbolAddress((void**)&xs_hi, g_xs_hi);
    cudaGetSymbolAddress((void**)&xs_lo, g_xs_lo);
    cudaGetSymbolAddress((void**)&qkvh, g_qkvh);
    cudaGetSymbolAddress((void**)&qkvl, g_qkvl);
    cudaGetSymbolAddress((void**)&ys_hi, g_ys_hi);
    cudaGetSymbolAddress((void**)&ys_lo, g_ys_lo);
    cudaGetSymbolAddress((void**)&wt_hi, g_wt_hi);
    cudaGetSymbolAddress((void**)&wt_lo, g_wt_lo);
    cudaGetSymbolAddress((void**)&bqkv, g_bqkv);

    static bool attr_set = false;
    if (!attr_set) {
        cudaFuncSetAttribute(gemm_hmma_kernel,
                             cudaFuncAttributeMaxDynamicSharedMemorySize, 2*GST);
        cudaFuncSetAttribute(attn_tc_kernel,
                             cudaFuncAttributeMaxDynamicSharedMemorySize, ASTAGE + 2*ASTS);
        attr_set = true;
    }

    const size_t WSZ = (size_t)DMODEL * DMODEL;

    dim3 wtGrid(DMODEL/32, DMODEL/32, 4), wtBlk(32, 8);
    wtsplit_kernel<<<wtGrid, wtBlk>>>(Wq, Wk, Wv, Wo, wt_hi, wt_lo);
    bcat_kernel<<<(NQKV + 255)/256, 256>>>(bq, bk, bv, bqkv);

    int n4 = NTOK * DMODEL / 4;
    fsplit_kernel<<<n4 / 256, 256>>>(x, xs_hi, xs_lo, n4);

    // Fused QKV projection: N = 2304
    dim3 qkvGrid(NQKV/64, NTOK/128);   // (36, 32) = 1152 CTAs
    gemm_hmma_kernel<<<qkvGrid, 256, 2*GST>>>(
        xs_hi, xs_lo, wt_hi, wt_lo, bqkv, nullptr, qkvh, qkvl, 1, NQKV);

    dim3 aGrid(NQB64, BATCH*NH);        // (32, 24) — fine-grained, heavy first
    attn_tc_kernel<<<aGrid, 128, ASTAGE + 2*ASTS>>>(qkvh, qkvl, ys_hi, ys_lo);

    dim3 oGrid(DMODEL/64, NTOK/128);    // (12, 32) = 384 CTAs
    gemm_hmma_kernel<<<oGrid, 256, 2*GST>>>(
        ys_hi, ys_lo, wt_hi + 3*WSZ, wt_lo + 3*WSZ, bo, out, nullptr, nullptr, 0, DMODEL);
}